// round 7
// baseline (speedup 1.0000x reference)
#include <cuda_runtime.h>
#include <cuda_bf16.h>
#include <math.h>
#include <stdint.h>

#define NUM_RANGES 256
#define KPR 512
#define DOPPLER 64
#define EMBED 16
#define IN_DIM 96
#define NROWS (NUM_RANGES * KPR)   // 131072

// Scratch (static device allocations are permitted)
__device__ __nv_bfloat16 g_Qh[NROWS * 64];
__device__ __nv_bfloat16 g_Ql[NROWS * 64];
__device__ __nv_bfloat16 g_Kh[NROWS * 64];
__device__ __nv_bfloat16 g_Kl[NROWS * 64];
__device__ float g_vs[NROWS];
__device__ float2 g_part[NROWS * 4];   // per-(row, k-slice) partial (se, sv)

// ---------------- mma.sync / ldmatrix helpers (sm_80+ PTX, sm_103-safe) -----
__device__ __forceinline__ unsigned smem_u32(const void* p) {
    unsigned a;
    asm("{ .reg .u64 t; cvta.to.shared.u64 t, %1; cvt.u32.u64 %0, t; }" : "=r"(a) : "l"(p));
    return a;
}
__device__ __forceinline__ void ldsm_x4(uint32_t* r, unsigned addr) {
    asm volatile("ldmatrix.sync.aligned.m8n8.x4.shared.b16 {%0,%1,%2,%3}, [%4];"
                 : "=r"(r[0]), "=r"(r[1]), "=r"(r[2]), "=r"(r[3]) : "r"(addr));
}
__device__ __forceinline__ void mma_bf16(float* c, const uint32_t* a, const uint32_t* b) {
    asm volatile("mma.sync.aligned.m16n8k16.row.col.f32.bf16.bf16.f32 "
                 "{%0,%1,%2,%3}, {%4,%5,%6,%7}, {%8,%9}, {%0,%1,%2,%3};"
                 : "+f"(c[0]), "+f"(c[1]), "+f"(c[2]), "+f"(c[3])
                 : "r"(a[0]), "r"(a[1]), "r"(a[2]), "r"(a[3]), "r"(b[0]), "r"(b[1]));
}
__device__ __forceinline__ float ex2(float x) {
    float y; asm("ex2.approx.f32 %0, %1;" : "=f"(y) : "f"(x)); return y;
}
__device__ __forceinline__ void bsplit(float v, __nv_bfloat16& h, __nv_bfloat16& l) {
    h = __float2bfloat16_rn(v);
    l = __float2bfloat16_rn(v - __bfloat162float(h));
}

#define SCQ 0.1803368801111244f   // log2(e) / sqrt(64)

// ---------------------------------------------------------------------------
// Kernel A: fused gather + QK projection via mma.sync, 512 threads.
// Warp (g,h): q rows g*16..+15, output cols h*64..+63. vsum parallel on all thr.
// ---------------------------------------------------------------------------
#define QP 104
#define AX_H 0
#define AX_L (AX_H + 128 * QP * 2)          // 26624
#define AW_H (AX_L + 128 * QP * 2)          // 53248
#define AW_L (AW_H + 128 * QP * 2)          // 79872
#define A_WV (AW_L + 128 * QP * 2)          // 106496  float[96]
#define A_BB (A_WV + 96 * 4)                // 106880  float[128]
#define A_BVS (A_BB + 128 * 4)              // 107392  float[1]
#define A_SMEM_BYTES (A_BVS + 128)          // 107520

__global__ void __launch_bounds__(512, 1) qkv_mma_kernel(
    const float* __restrict__ power, const int* __restrict__ ele_idx,
    const int* __restrict__ azi_idx, const float* __restrict__ ele_tab,
    const float* __restrict__ azi_tab,
    const float* __restrict__ Wq, const float* __restrict__ bq,
    const float* __restrict__ Wk, const float* __restrict__ bk,
    const float* __restrict__ Wv, const float* __restrict__ bv)
{
    extern __shared__ char smem[];
    const unsigned sbase = smem_u32(smem);
    __nv_bfloat16* xh = (__nv_bfloat16*)(smem + AX_H);
    __nv_bfloat16* xl = (__nv_bfloat16*)(smem + AX_L);
    __nv_bfloat16* wh = (__nv_bfloat16*)(smem + AW_H);
    __nv_bfloat16* wl = (__nv_bfloat16*)(smem + AW_L);
    float* sWv  = (float*)(smem + A_WV);
    float* sB   = (float*)(smem + A_BB);
    float* sBvs = (float*)(smem + A_BVS);

    const int tid  = threadIdx.x;
    const int row0 = blockIdx.x * 128;

    // gather + split x
    for (int i = tid; i < 128 * DOPPLER; i += 512) {
        int r = i >> 6, f = i & 63;
        __nv_bfloat16 h, l;
        bsplit(power[(size_t)(row0 + r) * DOPPLER + f], h, l);
        xh[r * QP + f] = h; xl[r * QP + f] = l;
    }
    for (int i = tid; i < 128 * 2 * EMBED; i += 512) {
        int r = i >> 5, e = i & 31;
        int row = row0 + r;
        float v; int f;
        if (e < EMBED) { v = ele_tab[ele_idx[row] * EMBED + e];          f = 64 + e; }
        else           { v = azi_tab[azi_idx[row] * EMBED + (e - EMBED)]; f = 80 + (e - EMBED); }
        __nv_bfloat16 h, l; bsplit(v, h, l);
        xh[r * QP + f] = h; xl[r * QP + f] = l;
    }
    // weights: rows 0..63 = Wq, 64..127 = Wk
    for (int i = tid; i < 64 * 96; i += 512) {
        int d = i / 96, f = i % 96;
        __nv_bfloat16 h, l;
        bsplit(Wq[i], h, l); wh[d * QP + f] = h;        wl[d * QP + f] = l;
        bsplit(Wk[i], h, l); wh[(64 + d) * QP + f] = h; wl[(64 + d) * QP + f] = l;
    }
    if (tid < 96) {
        float s = 0.f;
        #pragma unroll 8
        for (int d = 0; d < 64; ++d) s += Wv[d * 96 + tid];
        sWv[tid] = s;
    }
    if (tid < 64)       sB[tid] = bq[tid];
    else if (tid < 128) sB[tid] = bk[tid - 64];
    if (tid == 0) {
        float s = 0.f;
        #pragma unroll 8
        for (int d = 0; d < 64; ++d) s += bv[d];
        *sBvs = s;
    }
    __syncthreads();

    // vsum: 2 threads per row (48 features each), combine via shfl
    if (tid < 256) {
        int row = tid >> 1;
        int f0 = (tid & 1) * 48;
        float acc = 0.f;
        #pragma unroll 4
        for (int f = f0; f < f0 + 48; ++f)
            acc += (__bfloat162float(xh[row * QP + f]) + __bfloat162float(xl[row * QP + f])) * sWv[f];
        acc += __shfl_xor_sync(0xffffffffu, acc, 1);
        if ((tid & 1) == 0) g_vs[row0 + row] = acc + *sBvs;
    }

    // ---- MMA: warp (g,h): rows g*16..+15, out cols h*64..+63, K=96 ----
    const int w = tid >> 5, lane = tid & 31;
    const int g = w >> 1, h = w & 1;
    const int qr = g * 16;
    const int arow = qr + (lane & 15);
    const int acol = (lane >> 4) * 8;
    const int brow = (lane & 7) + ((lane >> 4) << 3);
    const int bcol = ((lane >> 3) & 1) * 8;

    float C[8][4];
    #pragma unroll
    for (int nt = 0; nt < 8; ++nt)
        #pragma unroll
        for (int j = 0; j < 4; ++j) C[nt][j] = 0.f;

    #pragma unroll
    for (int dc = 0; dc < 6; ++dc) {
        uint32_t Ah[4], Al[4];
        unsigned aoff = (unsigned)(arow * QP + dc * 16 + acol) * 2;
        ldsm_x4(Ah, sbase + AX_H + aoff);
        ldsm_x4(Al, sbase + AX_L + aoff);
        #pragma unroll
        for (int nt2 = 0; nt2 < 4; ++nt2) {
            unsigned boff = (unsigned)((h * 64 + nt2 * 16 + brow) * QP + dc * 16 + bcol) * 2;
            uint32_t Bh[4], Bl[4];
            ldsm_x4(Bh, sbase + AW_H + boff);
            ldsm_x4(Bl, sbase + AW_L + boff);
            mma_bf16(C[nt2 * 2],     Ah, Bh);
            mma_bf16(C[nt2 * 2 + 1], Ah, Bh + 2);
            mma_bf16(C[nt2 * 2],     Ah, Bl);
            mma_bf16(C[nt2 * 2 + 1], Ah, Bl + 2);
            mma_bf16(C[nt2 * 2],     Al, Bh);
            mma_bf16(C[nt2 * 2 + 1], Al, Bh + 2);
        }
    }

    // ---- epilogue: bias + scale + hi/lo split + packed bf16x2 stores ----
    const int r0 = row0 + qr + (lane >> 2);
    const bool isQ = (h == 0);
    const float scl = isQ ? SCQ : 1.0f;
    __nv_bfloat16* gh = isQ ? g_Qh : g_Kh;
    __nv_bfloat16* gl = isQ ? g_Ql : g_Kl;
    #pragma unroll
    for (int nt = 0; nt < 8; ++nt) {
        int cb = h * 64 + nt * 8 + (lane & 3) * 2;   // global out col
        int cc = isQ ? cb : (cb - 64);
        float b0 = sB[cb], b1 = sB[cb + 1];
        float v00 = (C[nt][0] + b0) * scl, v01 = (C[nt][1] + b1) * scl;
        float v10 = (C[nt][2] + b0) * scl, v11 = (C[nt][3] + b1) * scl;
        __nv_bfloat16 h0, l0, h1, l1;
        bsplit(v00, h0, l0); bsplit(v01, h1, l1);
        *(unsigned*)&gh[(size_t)r0 * 64 + cc] =
            (unsigned)__bfloat16_as_ushort(h0) | ((unsigned)__bfloat16_as_ushort(h1) << 16);
        *(unsigned*)&gl[(size_t)r0 * 64 + cc] =
            (unsigned)__bfloat16_as_ushort(l0) | ((unsigned)__bfloat16_as_ushort(l1) << 16);
        bsplit(v10, h0, l0); bsplit(v11, h1, l1);
        *(unsigned*)&gh[(size_t)(r0 + 8) * 64 + cc] =
            (unsigned)__bfloat16_as_ushort(h0) | ((unsigned)__bfloat16_as_ushort(h1) << 16);
        *(unsigned*)&gl[(size_t)(r0 + 8) * 64 + cc] =
            (unsigned)__bfloat16_as_ushort(l0) | ((unsigned)__bfloat16_as_ushort(l1) << 16);
    }
}

// ---------------------------------------------------------------------------
// Kernel B: mma.sync bf16-split attention, 256 threads, 128q x 128k per CTA.
// grid = 4096: r = bid>>4, qb = (bid>>2)&3, kb = bid&3.
// Warp w: 16 q rows, all 128 k of this CTA's slice. A-frags resident.
// 32k-column chunks keep C at 16 regs -> 3 CTAs/SM (24 warps).
// Partials (se, sv) written to g_part (distinct addresses), merged by finalize.
// ---------------------------------------------------------------------------
#define QS 72
#define S_QH 0
#define S_QL (S_QH + 128 * QS * 2)          // 18432
#define S_KH (S_QL + 128 * QS * 2)          // 36864
#define S_KL (S_KH + 128 * QS * 2)          // 55296
#define S_VS (S_KL + 128 * QS * 2)          // 73728
#define B_SMEM_BYTES (S_VS + 128 * 4)       // 74240

__global__ void __launch_bounds__(256, 3) attn_mma_kernel()
{
    extern __shared__ char smem[];
    const unsigned sbase = smem_u32(smem);
    const int tid = threadIdx.x;
    const int r  = blockIdx.x >> 4;
    const int qb = (blockIdx.x >> 2) & 3;
    const int kb = blockIdx.x & 3;
    const int kbase = r * KPR;
    const int qrow0 = kbase + qb * 128;
    const int krow0 = kbase + kb * 128;

    // ---- load Q (hi/lo), K-slice (hi/lo), vsum-slice into smem ----
    {
        const uint4* Qh4 = (const uint4*)g_Qh;
        const uint4* Ql4 = (const uint4*)g_Ql;
        const uint4* Kh4 = (const uint4*)g_Kh;
        const uint4* Kl4 = (const uint4*)g_Kl;
        for (int i = tid; i < 1024; i += 256) {
            int row = i >> 3, c = i & 7;
            unsigned off = row * QS * 2 + c * 16;
            size_t gq = (size_t)(qrow0 + row) * 8 + c;
            size_t gk = (size_t)(krow0 + row) * 8 + c;
            *(uint4*)(smem + S_QH + off) = Qh4[gq];
            *(uint4*)(smem + S_QL + off) = Ql4[gq];
            *(uint4*)(smem + S_KH + off) = Kh4[gk];
            *(uint4*)(smem + S_KL + off) = Kl4[gk];
        }
        if (tid < 128)
            *(float*)(smem + S_VS + tid * 4) = g_vs[krow0 + tid];
    }
    __syncthreads();

    const int w = tid >> 5, lane = tid & 31;
    const int qr = w * 16;

    // ---- resident A fragments (Qh, Ql), 4 d-chunks ----
    uint32_t Ah[4][4], Al[4][4];
    {
        int arow = qr + (lane & 15);
        int acol = (lane >> 4) * 8;
        #pragma unroll
        for (int dc = 0; dc < 4; ++dc) {
            unsigned off = (unsigned)(arow * QS + dc * 16 + acol) * 2;
            ldsm_x4(Ah[dc], sbase + S_QH + off);
            ldsm_x4(Al[dc], sbase + S_QL + off);
        }
    }

    float se0 = 0.f, sv0 = 0.f, se1 = 0.f, sv1 = 0.f;
    const int brow = (lane & 7) + ((lane >> 4) << 3);
    const int bcol = ((lane >> 3) & 1) * 8;
    const float* vsp = (const float*)(smem + S_VS);
    const int c0off = 2 * (lane & 3);

    #pragma unroll
    for (int kt = 0; kt < 4; ++kt) {          // 32 k-cols per chunk
        float C[4][4];
        #pragma unroll
        for (int nt = 0; nt < 4; ++nt)
            #pragma unroll
            for (int j = 0; j < 4; ++j) C[nt][j] = 0.f;

        #pragma unroll
        for (int dc = 0; dc < 4; ++dc) {
            #pragma unroll
            for (int nt2 = 0; nt2 < 2; ++nt2) {
                int n0 = kt * 32 + nt2 * 16;
                unsigned off = (unsigned)((n0 + brow) * QS + dc * 16 + bcol) * 2;
                uint32_t Bh[4], Bl[4];
                ldsm_x4(Bh, sbase + S_KH + off);
                ldsm_x4(Bl, sbase + S_KL + off);
                mma_bf16(C[nt2 * 2],     Ah[dc], Bh);
                mma_bf16(C[nt2 * 2 + 1], Ah[dc], Bh + 2);
                mma_bf16(C[nt2 * 2],     Ah[dc], Bl);
                mma_bf16(C[nt2 * 2 + 1], Ah[dc], Bl + 2);
                mma_bf16(C[nt2 * 2],     Al[dc], Bh);
                mma_bf16(C[nt2 * 2 + 1], Al[dc], Bh + 2);
            }
        }

        // epilogue for this 32-k chunk (scores already in log2 units)
        #pragma unroll
        for (int nt = 0; nt < 4; ++nt) {
            int col0 = kt * 32 + nt * 8 + c0off;
            float2 vv = *(const float2*)(vsp + col0);
            float e0 = ex2(C[nt][0]);
            float e1 = ex2(C[nt][1]);
            float e2 = ex2(C[nt][2]);
            float e3 = ex2(C[nt][3]);
            se0 += e0 + e1; sv0 += e0 * vv.x + e1 * vv.y;
            se1 += e2 + e3; sv1 += e2 * vv.x + e3 * vv.y;
        }
    }

    // quad reduce, then write k-slice partials (distinct addresses, no atomics)
    #pragma unroll
    for (int o = 1; o <= 2; o <<= 1) {
        se0 += __shfl_xor_sync(0xffffffffu, se0, o);
        sv0 += __shfl_xor_sync(0xffffffffu, sv0, o);
        se1 += __shfl_xor_sync(0xffffffffu, se1, o);
        sv1 += __shfl_xor_sync(0xffffffffu, sv1, o);
    }
    if ((lane & 3) == 0) {
        int row = qrow0 + qr + (lane >> 2);
        g_part[(size_t)row * 4 + kb]       = make_float2(se0, sv0);
        g_part[(size_t)(row + 8) * 4 + kb] = make_float2(se1, sv1);
    }
}

// ---------------------------------------------------------------------------
// Finalize: merge the 4 k-slice partials per row.
// ---------------------------------------------------------------------------
__global__ void __launch_bounds__(256) finalize_kernel(float* __restrict__ out)
{
    int i = blockIdx.x * 256 + threadIdx.x;
    const float4* p = (const float4*)(g_part + (size_t)i * 4);
    float4 a = p[0], b = p[1];   // (se0,sv0,se1,sv1), (se2,sv2,se3,sv3)
    out[i] = (a.y + a.w + b.y + b.w) / (a.x + a.z + b.x + b.z);
}

// ---------------------------------------------------------------------------
// Launch
// ---------------------------------------------------------------------------
extern "C" void kernel_launch(void* const* d_in, const int* in_sizes, int n_in,
                              void* d_out, int out_size)
{
    const float* power   = (const float*)d_in[0];
    const int*   ele_idx = (const int*)  d_in[1];
    // d_in[2] = range_indices (unused by reference)
    const int*   azi_idx = (const int*)  d_in[3];
    const float* ele_tab = (const float*)d_in[4];
    const float* azi_tab = (const float*)d_in[5];
    const float* Wq      = (const float*)d_in[6];
    const float* bq      = (const float*)d_in[7];
    const float* Wk      = (const float*)d_in[8];
    const float* bk      = (const float*)d_in[9];
    const float* Wv      = (const float*)d_in[10];
    const float* bv      = (const float*)d_in[11];
    float* out = (float*)d_out;

    cudaFuncSetAttribute(qkv_mma_kernel, cudaFuncAttributeMaxDynamicSharedMemorySize, A_SMEM_BYTES);
    cudaFuncSetAttribute(attn_mma_kernel, cudaFuncAttributeMaxDynamicSharedMemorySize, B_SMEM_BYTES);

    qkv_mma_kernel<<<NROWS / 128, 512, A_SMEM_BYTES>>>(
        power, ele_idx, azi_idx, ele_tab, azi_tab, Wq, bq, Wk, bk, Wv, bv);
    attn_mma_kernel<<<NUM_RANGES * 16, 256, B_SMEM_BYTES>>>();
    finalize_kernel<<<NROWS / 256, 256>>>(out);
}

// round 8
// speedup vs baseline: 1.2649x; 1.2649x over previous
#include <cuda_runtime.h>
#include <cuda_bf16.h>
#include <math.h>
#include <stdint.h>

#define NUM_RANGES 256
#define KPR 512
#define DOPPLER 64
#define EMBED 16
#define IN_DIM 96
#define NROWS (NUM_RANGES * KPR)   // 131072

// Scratch (static device allocations are permitted)
__device__ __nv_bfloat16 g_Qh[NROWS * 64];
__device__ __nv_bfloat16 g_Ql[NROWS * 64];
__device__ __nv_bfloat16 g_Kh[NROWS * 64];
__device__ __nv_bfloat16 g_Kl[NROWS * 64];
__device__ float g_vs[NROWS];
__device__ float2 g_part[NROWS * 4];        // per-(row, k-slice) partial (se, sv)
__device__ __nv_bfloat16 g_Wh[128 * 96];    // pre-split weights (rows 0..63 Wq, 64..127 Wk)
__device__ __nv_bfloat16 g_Wl[128 * 96];
__device__ float g_wvs[96];
__device__ float g_bb[128];
__device__ float g_bvs[1];

// ---------------- mma.sync / ldmatrix helpers (sm_80+ PTX, sm_103-safe) -----
__device__ __forceinline__ unsigned smem_u32(const void* p) {
    unsigned a;
    asm("{ .reg .u64 t; cvta.to.shared.u64 t, %1; cvt.u32.u64 %0, t; }" : "=r"(a) : "l"(p));
    return a;
}
__device__ __forceinline__ void ldsm_x4(uint32_t* r, unsigned addr) {
    asm volatile("ldmatrix.sync.aligned.m8n8.x4.shared.b16 {%0,%1,%2,%3}, [%4];"
                 : "=r"(r[0]), "=r"(r[1]), "=r"(r[2]), "=r"(r[3]) : "r"(addr));
}
__device__ __forceinline__ void mma_bf16(float* c, const uint32_t* a, const uint32_t* b) {
    asm volatile("mma.sync.aligned.m16n8k16.row.col.f32.bf16.bf16.f32 "
                 "{%0,%1,%2,%3}, {%4,%5,%6,%7}, {%8,%9}, {%0,%1,%2,%3};"
                 : "+f"(c[0]), "+f"(c[1]), "+f"(c[2]), "+f"(c[3])
                 : "r"(a[0]), "r"(a[1]), "r"(a[2]), "r"(a[3]), "r"(b[0]), "r"(b[1]));
}
__device__ __forceinline__ float ex2(float x) {
    float y; asm("ex2.approx.f32 %0, %1;" : "=f"(y) : "f"(x)); return y;
}
__device__ __forceinline__ void bsplit(float v, __nv_bfloat16& h, __nv_bfloat16& l) {
    h = __float2bfloat16_rn(v);
    l = __float2bfloat16_rn(v - __bfloat162float(h));
}

#define SCQ 0.1803368801111244f   // log2(e) / sqrt(64)

// ---------------------------------------------------------------------------
// Prep kernel: one-time weight split + wv colsums + bias staging.
// ---------------------------------------------------------------------------
__global__ void __launch_bounds__(128) prep_kernel(
    const float* __restrict__ Wq, const float* __restrict__ bq,
    const float* __restrict__ Wk, const float* __restrict__ bk,
    const float* __restrict__ Wv, const float* __restrict__ bv)
{
    const int tid = threadIdx.x;
    for (int i = tid; i < 64 * 96; i += 128) {
        int d = i / 96, f = i % 96;
        __nv_bfloat16 h, l;
        bsplit(Wq[i], h, l); g_Wh[d * 96 + f] = h;        g_Wl[d * 96 + f] = l;
        bsplit(Wk[i], h, l); g_Wh[(64 + d) * 96 + f] = h; g_Wl[(64 + d) * 96 + f] = l;
    }
    if (tid < 96) {
        float s = 0.f;
        #pragma unroll 8
        for (int d = 0; d < 64; ++d) s += Wv[d * 96 + tid];
        g_wvs[tid] = s;
    }
    if (tid < 64) { g_bb[tid] = bq[tid]; g_bb[64 + tid] = bk[tid]; }
    if (tid == 0) {
        float s = 0.f;
        #pragma unroll 8
        for (int d = 0; d < 64; ++d) s += bv[d];
        g_bvs[0] = s;
    }
}

// ---------------------------------------------------------------------------
// Kernel A: fused gather + QK projection via mma.sync.
// CTA = 128 rows x 128 outs x 96, 256 thr, 2 CTAs/SM (phase overlap).
// Weights pre-split by prep_kernel (bf16 uint4 copies).
// ---------------------------------------------------------------------------
#define QP 104
#define AX_H 0
#define AX_L (AX_H + 128 * QP * 2)          // 26624
#define AW_H (AX_L + 128 * QP * 2)          // 53248
#define AW_L (AW_H + 128 * QP * 2)          // 79872
#define A_WV (AW_L + 128 * QP * 2)          // 106496  float[96]
#define A_BB (A_WV + 96 * 4)                // 106880  float[128]
#define A_BVS (A_BB + 128 * 4)              // 107392  float[1]
#define A_SMEM_BYTES (A_BVS + 128)          // 107520

__global__ void __launch_bounds__(256, 2) qkv_mma_kernel(
    const float* __restrict__ power, const int* __restrict__ ele_idx,
    const int* __restrict__ azi_idx, const float* __restrict__ ele_tab,
    const float* __restrict__ azi_tab)
{
    extern __shared__ char smem[];
    const unsigned sbase = smem_u32(smem);
    __nv_bfloat16* xh = (__nv_bfloat16*)(smem + AX_H);
    __nv_bfloat16* xl = (__nv_bfloat16*)(smem + AX_L);
    float* sWv  = (float*)(smem + A_WV);
    float* sB   = (float*)(smem + A_BB);
    float* sBvs = (float*)(smem + A_BVS);

    const int tid  = threadIdx.x;
    const int row0 = blockIdx.x * 128;

    // gather + split x
    for (int i = tid; i < 128 * DOPPLER; i += 256) {
        int r = i >> 6, f = i & 63;
        __nv_bfloat16 h, l;
        bsplit(power[(size_t)(row0 + r) * DOPPLER + f], h, l);
        xh[r * QP + f] = h; xl[r * QP + f] = l;
    }
    for (int i = tid; i < 128 * 2 * EMBED; i += 256) {
        int r = i >> 5, e = i & 31;
        int row = row0 + r;
        float v; int f;
        if (e < EMBED) { v = ele_tab[ele_idx[row] * EMBED + e];          f = 64 + e; }
        else           { v = azi_tab[azi_idx[row] * EMBED + (e - EMBED)]; f = 80 + (e - EMBED); }
        __nv_bfloat16 h, l; bsplit(v, h, l);
        xh[r * QP + f] = h; xl[r * QP + f] = l;
    }
    // weights: straight bf16 copies (12 uint4 chunks per 96-elem row)
    for (int i = tid; i < 128 * 12; i += 256) {
        int row = i / 12, c = i % 12;
        *(uint4*)(smem + AW_H + row * QP * 2 + c * 16) = *(const uint4*)&g_Wh[row * 96 + c * 8];
        *(uint4*)(smem + AW_L + row * QP * 2 + c * 16) = *(const uint4*)&g_Wl[row * 96 + c * 8];
    }
    if (tid < 96)  sWv[tid] = g_wvs[tid];
    if (tid < 128) sB[tid]  = g_bb[tid];
    if (tid == 0)  *sBvs = g_bvs[0];
    __syncthreads();

    // vsum: 2 threads per row (48 features each), combine via shfl
    if (tid < 256) {
        int row = tid >> 1;
        int f0 = (tid & 1) * 48;
        float acc = 0.f;
        #pragma unroll 4
        for (int f = f0; f < f0 + 48; ++f)
            acc += (__bfloat162float(xh[row * QP + f]) + __bfloat162float(xl[row * QP + f])) * sWv[f];
        acc += __shfl_xor_sync(0xffffffffu, acc, 1);
        if ((tid & 1) == 0) g_vs[row0 + row] = acc + *sBvs;
    }

    // ---- MMA: warp w = rows w*16..+15, all 128 outs, K=96 (6 chunks) ----
    const int w = tid >> 5, lane = tid & 31;
    const int qr = w * 16;
    const int arow = qr + (lane & 15);
    const int acol = (lane >> 4) * 8;
    const int brow = (lane & 7) + ((lane >> 4) << 3);
    const int bcol = ((lane >> 3) & 1) * 8;

    float C[16][4];
    #pragma unroll
    for (int nt = 0; nt < 16; ++nt)
        #pragma unroll
        for (int j = 0; j < 4; ++j) C[nt][j] = 0.f;

    #pragma unroll
    for (int dc = 0; dc < 6; ++dc) {
        uint32_t Ah[4], Al[4];
        unsigned aoff = (unsigned)(arow * QP + dc * 16 + acol) * 2;
        ldsm_x4(Ah, sbase + AX_H + aoff);
        ldsm_x4(Al, sbase + AX_L + aoff);
        #pragma unroll
        for (int nt2 = 0; nt2 < 8; ++nt2) {
            unsigned boff = (unsigned)((nt2 * 16 + brow) * QP + dc * 16 + bcol) * 2;
            uint32_t Bh[4], Bl[4];
            ldsm_x4(Bh, sbase + AW_H + boff);
            ldsm_x4(Bl, sbase + AW_L + boff);
            mma_bf16(C[nt2 * 2],     Ah, Bh);
            mma_bf16(C[nt2 * 2 + 1], Ah, Bh + 2);
            mma_bf16(C[nt2 * 2],     Ah, Bl);
            mma_bf16(C[nt2 * 2 + 1], Ah, Bl + 2);
            mma_bf16(C[nt2 * 2],     Al, Bh);
            mma_bf16(C[nt2 * 2 + 1], Al, Bh + 2);
        }
    }

    // ---- epilogue: bias + scale + hi/lo split + packed bf16x2 stores ----
    const int r0 = row0 + qr + (lane >> 2);
    #pragma unroll
    for (int nt = 0; nt < 16; ++nt) {
        int cb = nt * 8 + (lane & 3) * 2;
        bool isQ = (nt < 8);
        float scl = isQ ? SCQ : 1.0f;
        int cc = isQ ? cb : (cb - 64);
        __nv_bfloat16* gh = isQ ? g_Qh : g_Kh;
        __nv_bfloat16* gl = isQ ? g_Ql : g_Kl;
        float b0 = sB[cb], b1 = sB[cb + 1];
        float v00 = (C[nt][0] + b0) * scl, v01 = (C[nt][1] + b1) * scl;
        float v10 = (C[nt][2] + b0) * scl, v11 = (C[nt][3] + b1) * scl;
        __nv_bfloat16 h0, l0, h1, l1;
        bsplit(v00, h0, l0); bsplit(v01, h1, l1);
        *(unsigned*)&gh[(size_t)r0 * 64 + cc] =
            (unsigned)__bfloat16_as_ushort(h0) | ((unsigned)__bfloat16_as_ushort(h1) << 16);
        *(unsigned*)&gl[(size_t)r0 * 64 + cc] =
            (unsigned)__bfloat16_as_ushort(l0) | ((unsigned)__bfloat16_as_ushort(l1) << 16);
        bsplit(v10, h0, l0); bsplit(v11, h1, l1);
        *(unsigned*)&gh[(size_t)(r0 + 8) * 64 + cc] =
            (unsigned)__bfloat16_as_ushort(h0) | ((unsigned)__bfloat16_as_ushort(h1) << 16);
        *(unsigned*)&gl[(size_t)(r0 + 8) * 64 + cc] =
            (unsigned)__bfloat16_as_ushort(l0) | ((unsigned)__bfloat16_as_ushort(l1) << 16);
    }
}

// ---------------------------------------------------------------------------
// Kernel B: mma.sync bf16-split attention, 256 threads, 128q x 128k per CTA.
// grid = 4096: r = bid>>4, qb = (bid>>2)&3, kb = bid&3. 3 CTAs/SM.
// ---------------------------------------------------------------------------
#define QS 72
#define S_QH 0
#define S_QL (S_QH + 128 * QS * 2)          // 18432
#define S_KH (S_QL + 128 * QS * 2)          // 36864
#define S_KL (S_KH + 128 * QS * 2)          // 55296
#define S_VS (S_KL + 128 * QS * 2)          // 73728
#define B_SMEM_BYTES (S_VS + 128 * 4)       // 74240

__global__ void __launch_bounds__(256, 3) attn_mma_kernel()
{
    extern __shared__ char smem[];
    const unsigned sbase = smem_u32(smem);
    const int tid = threadIdx.x;
    const int r  = blockIdx.x >> 4;
    const int qb = (blockIdx.x >> 2) & 3;
    const int kb = blockIdx.x & 3;
    const int kbase = r * KPR;
    const int qrow0 = kbase + qb * 128;
    const int krow0 = kbase + kb * 128;

    // ---- load Q (hi/lo), K-slice (hi/lo), vsum-slice into smem ----
    {
        const uint4* Qh4 = (const uint4*)g_Qh;
        const uint4* Ql4 = (const uint4*)g_Ql;
        const uint4* Kh4 = (const uint4*)g_Kh;
        const uint4* Kl4 = (const uint4*)g_Kl;
        for (int i = tid; i < 1024; i += 256) {
            int row = i >> 3, c = i & 7;
            unsigned off = row * QS * 2 + c * 16;
            size_t gq = (size_t)(qrow0 + row) * 8 + c;
            size_t gk = (size_t)(krow0 + row) * 8 + c;
            *(uint4*)(smem + S_QH + off) = Qh4[gq];
            *(uint4*)(smem + S_QL + off) = Ql4[gq];
            *(uint4*)(smem + S_KH + off) = Kh4[gk];
            *(uint4*)(smem + S_KL + off) = Kl4[gk];
        }
        if (tid < 128)
            *(float*)(smem + S_VS + tid * 4) = g_vs[krow0 + tid];
    }
    __syncthreads();

    const int w = tid >> 5, lane = tid & 31;
    const int qr = w * 16;

    // ---- resident A fragments (Qh, Ql), 4 d-chunks ----
    uint32_t Ah[4][4], Al[4][4];
    {
        int arow = qr + (lane & 15);
        int acol = (lane >> 4) * 8;
        #pragma unroll
        for (int dc = 0; dc < 4; ++dc) {
            unsigned off = (unsigned)(arow * QS + dc * 16 + acol) * 2;
            ldsm_x4(Ah[dc], sbase + S_QH + off);
            ldsm_x4(Al[dc], sbase + S_QL + off);
        }
    }

    float se0 = 0.f, sv0 = 0.f, se1 = 0.f, sv1 = 0.f;
    const int brow = (lane & 7) + ((lane >> 4) << 3);
    const int bcol = ((lane >> 3) & 1) * 8;
    const float* vsp = (const float*)(smem + S_VS);
    const int c0off = 2 * (lane & 3);

    #pragma unroll
    for (int kt = 0; kt < 4; ++kt) {          // 32 k-cols per chunk
        float C[4][4];
        #pragma unroll
        for (int nt = 0; nt < 4; ++nt)
            #pragma unroll
            for (int j = 0; j < 4; ++j) C[nt][j] = 0.f;

        #pragma unroll
        for (int dc = 0; dc < 4; ++dc) {
            #pragma unroll
            for (int nt2 = 0; nt2 < 2; ++nt2) {
                int n0 = kt * 32 + nt2 * 16;
                unsigned off = (unsigned)((n0 + brow) * QS + dc * 16 + bcol) * 2;
                uint32_t Bh[4], Bl[4];
                ldsm_x4(Bh, sbase + S_KH + off);
                ldsm_x4(Bl, sbase + S_KL + off);
                mma_bf16(C[nt2 * 2],     Ah[dc], Bh);
                mma_bf16(C[nt2 * 2 + 1], Ah[dc], Bh + 2);
                mma_bf16(C[nt2 * 2],     Ah[dc], Bl);
                mma_bf16(C[nt2 * 2 + 1], Ah[dc], Bl + 2);
                mma_bf16(C[nt2 * 2],     Al[dc], Bh);
                mma_bf16(C[nt2 * 2 + 1], Al[dc], Bh + 2);
            }
        }

        // epilogue for this 32-k chunk (scores already in log2 units)
        #pragma unroll
        for (int nt = 0; nt < 4; ++nt) {
            int col0 = kt * 32 + nt * 8 + c0off;
            float2 vv = *(const float2*)(vsp + col0);
            float e0 = ex2(C[nt][0]);
            float e1 = ex2(C[nt][1]);
            float e2 = ex2(C[nt][2]);
            float e3 = ex2(C[nt][3]);
            se0 += e0 + e1; sv0 += e0 * vv.x + e1 * vv.y;
            se1 += e2 + e3; sv1 += e2 * vv.x + e3 * vv.y;
        }
    }

    // quad reduce, then write k-slice partials (distinct addresses, no atomics)
    #pragma unroll
    for (int o = 1; o <= 2; o <<= 1) {
        se0 += __shfl_xor_sync(0xffffffffu, se0, o);
        sv0 += __shfl_xor_sync(0xffffffffu, sv0, o);
        se1 += __shfl_xor_sync(0xffffffffu, se1, o);
        sv1 += __shfl_xor_sync(0xffffffffu, sv1, o);
    }
    if ((lane & 3) == 0) {
        int row = qrow0 + qr + (lane >> 2);
        g_part[(size_t)row * 4 + kb]       = make_float2(se0, sv0);
        g_part[(size_t)(row + 8) * 4 + kb] = make_float2(se1, sv1);
    }
}

// ---------------------------------------------------------------------------
// Finalize: merge the 4 k-slice partials per row.
// ---------------------------------------------------------------------------
__global__ void __launch_bounds__(256) finalize_kernel(float* __restrict__ out)
{
    int i = blockIdx.x * 256 + threadIdx.x;
    const float4* p = (const float4*)(g_part + (size_t)i * 4);
    float4 a = p[0], b = p[1];   // (se0,sv0,se1,sv1), (se2,sv2,se3,sv3)
    out[i] = (a.y + a.w + b.y + b.w) / (a.x + a.z + b.x + b.z);
}

// ---------------------------------------------------------------------------
// Launch
// ---------------------------------------------------------------------------
extern "C" void kernel_launch(void* const* d_in, const int* in_sizes, int n_in,
                              void* d_out, int out_size)
{
    const float* power   = (const float*)d_in[0];
    const int*   ele_idx = (const int*)  d_in[1];
    // d_in[2] = range_indices (unused by reference)
    const int*   azi_idx = (const int*)  d_in[3];
    const float* ele_tab = (const float*)d_in[4];
    const float* azi_tab = (const float*)d_in[5];
    const float* Wq      = (const float*)d_in[6];
    const float* bq      = (const float*)d_in[7];
    const float* Wk      = (const float*)d_in[8];
    const float* bk      = (const float*)d_in[9];
    const float* Wv      = (const float*)d_in[10];
    const float* bv      = (const float*)d_in[11];
    float* out = (float*)d_out;

    cudaFuncSetAttribute(qkv_mma_kernel, cudaFuncAttributeMaxDynamicSharedMemorySize, A_SMEM_BYTES);
    cudaFuncSetAttribute(attn_mma_kernel, cudaFuncAttributeMaxDynamicSharedMemorySize, B_SMEM_BYTES);

    prep_kernel<<<1, 128>>>(Wq, bq, Wk, bk, Wv, bv);
    qkv_mma_kernel<<<NROWS / 128, 256, A_SMEM_BYTES>>>(
        power, ele_idx, azi_idx, ele_tab, azi_tab);
    attn_mma_kernel<<<NUM_RANGES * 16, 256, B_SMEM_BYTES>>>();
    finalize_kernel<<<NROWS / 256, 256>>>(out);
}

// round 9
// speedup vs baseline: 1.5332x; 1.2121x over previous
#include <cuda_runtime.h>
#include <cuda_bf16.h>
#include <math.h>
#include <stdint.h>

#define NUM_RANGES 256
#define KPR 512
#define DOPPLER 64
#define EMBED 16
#define IN_DIM 96
#define NROWS (NUM_RANGES * KPR)   // 131072

// Scratch (static device allocations are permitted)
__device__ __nv_bfloat16 g_Qh[NROWS * 64];
__device__ __nv_bfloat16 g_Ql[NROWS * 64];
__device__ __nv_bfloat16 g_Kh[NROWS * 64];
__device__ __nv_bfloat16 g_Kl[NROWS * 64];
__device__ float g_vs[NROWS];
__device__ float2 g_part[NROWS * 4];        // per-(row, k-slice) partial (se, sv)
__device__ __nv_bfloat16 g_Wh[128 * 96];    // pre-split weights (rows 0..63 Wq, 64..127 Wk)
__device__ __nv_bfloat16 g_Wl[128 * 96];
__device__ float g_wvs[96];
__device__ float g_bb[128];
__device__ float g_bvs[1];

// ---------------- mma.sync / ldmatrix helpers (sm_80+ PTX, sm_103-safe) -----
__device__ __forceinline__ unsigned smem_u32(const void* p) {
    unsigned a;
    asm("{ .reg .u64 t; cvta.to.shared.u64 t, %1; cvt.u32.u64 %0, t; }" : "=r"(a) : "l"(p));
    return a;
}
__device__ __forceinline__ void ldsm_x4(uint32_t* r, unsigned addr) {
    asm volatile("ldmatrix.sync.aligned.m8n8.x4.shared.b16 {%0,%1,%2,%3}, [%4];"
                 : "=r"(r[0]), "=r"(r[1]), "=r"(r[2]), "=r"(r[3]) : "r"(addr));
}
__device__ __forceinline__ void mma_bf16(float* c, const uint32_t* a, const uint32_t* b) {
    asm volatile("mma.sync.aligned.m16n8k16.row.col.f32.bf16.bf16.f32 "
                 "{%0,%1,%2,%3}, {%4,%5,%6,%7}, {%8,%9}, {%0,%1,%2,%3};"
                 : "+f"(c[0]), "+f"(c[1]), "+f"(c[2]), "+f"(c[3])
                 : "r"(a[0]), "r"(a[1]), "r"(a[2]), "r"(a[3]), "r"(b[0]), "r"(b[1]));
}
__device__ __forceinline__ float ex2(float x) {
    float y; asm("ex2.approx.f32 %0, %1;" : "=f"(y) : "f"(x)); return y;
}
__device__ __forceinline__ void bsplit(float v, __nv_bfloat16& h, __nv_bfloat16& l) {
    h = __float2bfloat16_rn(v);
    l = __float2bfloat16_rn(v - __bfloat162float(h));
}
__device__ __forceinline__ unsigned pk(__nv_bfloat16 a, __nv_bfloat16 b) {
    return (unsigned)__bfloat16_as_ushort(a) | ((unsigned)__bfloat16_as_ushort(b) << 16);
}

#define SCQ 0.1803368801111244f   // log2(e) / sqrt(64)

// ---------------------------------------------------------------------------
// Prep kernel: one-time weight split + wv colsums + bias staging.
// ---------------------------------------------------------------------------
__global__ void __launch_bounds__(128) prep_kernel(
    const float* __restrict__ Wq, const float* __restrict__ bq,
    const float* __restrict__ Wk, const float* __restrict__ bk,
    const float* __restrict__ Wv, const float* __restrict__ bv)
{
    const int tid = threadIdx.x;
    for (int i = tid; i < 64 * 96; i += 128) {
        int d = i / 96, f = i % 96;
        __nv_bfloat16 h, l;
        bsplit(Wq[i], h, l); g_Wh[d * 96 + f] = h;        g_Wl[d * 96 + f] = l;
        bsplit(Wk[i], h, l); g_Wh[(64 + d) * 96 + f] = h; g_Wl[(64 + d) * 96 + f] = l;
    }
    if (tid < 96) {
        float s = 0.f;
        #pragma unroll 8
        for (int d = 0; d < 64; ++d) s += Wv[d * 96 + tid];
        g_wvs[tid] = s;
    }
    if (tid < 64) { g_bb[tid] = bq[tid]; g_bb[64 + tid] = bk[tid]; }
    if (tid == 0) {
        float s = 0.f;
        #pragma unroll 8
        for (int d = 0; d < 64; ++d) s += bv[d];
        g_bvs[0] = s;
    }
}

// ---------------------------------------------------------------------------
// Kernel A: fused gather + QK projection via mma.sync.
// CTA = 128 rows x 128 outs x 96, 256 thr, 2 CTAs/SM.
// Gather: 2 threads/row, vectorized float4 loads, vsum fused inline.
// Epilogue: stage packed bf16 in smem (conflict-free), coalesced STG.128 out.
// ---------------------------------------------------------------------------
#define QP 104
#define ST_P 144                            // staging row pitch (bytes)
#define AX_H 0
#define AX_L (AX_H + 128 * QP * 2)          // 26624
#define AW_H (AX_L + 128 * QP * 2)          // 53248
#define AW_L (AW_H + 128 * QP * 2)          // 79872
#define A_BB (AW_L + 128 * QP * 2)          // 106496  float[128]
#define A_SMEM_BYTES (A_BB + 128 * 4)       // 107008

__global__ void __launch_bounds__(256, 2) qkv_mma_kernel(
    const float* __restrict__ power, const int* __restrict__ ele_idx,
    const int* __restrict__ azi_idx, const float* __restrict__ ele_tab,
    const float* __restrict__ azi_tab)
{
    extern __shared__ char smem[];
    const unsigned sbase = smem_u32(smem);
    __nv_bfloat16* xh = (__nv_bfloat16*)(smem + AX_H);
    __nv_bfloat16* xl = (__nv_bfloat16*)(smem + AX_L);
    float* sB = (float*)(smem + A_BB);

    const int tid  = threadIdx.x;
    const int row0 = blockIdx.x * 128;

    // ---- fused gather + bf16 split + inline vsum (2 threads per row) ----
    {
        const int row = tid >> 1, half = tid & 1;
        const int grow = row0 + row;
        unsigned* xhrow = (unsigned*)(xh + row * QP);
        unsigned* xlrow = (unsigned*)(xl + row * QP);
        float vacc = 0.f;

        const float4* pv = (const float4*)(power + (size_t)grow * 64 + half * 32);
        #pragma unroll
        for (int u = 0; u < 8; ++u) {
            float4 v = pv[u];
            int f = half * 32 + u * 4;
            vacc += v.x * g_wvs[f]     + v.y * g_wvs[f + 1]
                  + v.z * g_wvs[f + 2] + v.w * g_wvs[f + 3];
            __nv_bfloat16 h0, l0, h1, l1;
            bsplit(v.x, h0, l0); bsplit(v.y, h1, l1);
            xhrow[f >> 1] = pk(h0, h1); xlrow[f >> 1] = pk(l0, l1);
            bsplit(v.z, h0, l0); bsplit(v.w, h1, l1);
            xhrow[(f >> 1) + 1] = pk(h0, h1); xlrow[(f >> 1) + 1] = pk(l0, l1);
        }
        const int eidx = half ? azi_idx[grow] : ele_idx[grow];
        const float4* ev = (const float4*)((half ? azi_tab : ele_tab) + (size_t)eidx * 16);
        const int fbase = 64 + half * 16;
        #pragma unroll
        for (int u = 0; u < 4; ++u) {
            float4 v = ev[u];
            int f = fbase + u * 4;
            vacc += v.x * g_wvs[f]     + v.y * g_wvs[f + 1]
                  + v.z * g_wvs[f + 2] + v.w * g_wvs[f + 3];
            __nv_bfloat16 h0, l0, h1, l1;
            bsplit(v.x, h0, l0); bsplit(v.y, h1, l1);
            xhrow[f >> 1] = pk(h0, h1); xlrow[f >> 1] = pk(l0, l1);
            bsplit(v.z, h0, l0); bsplit(v.w, h1, l1);
            xhrow[(f >> 1) + 1] = pk(h0, h1); xlrow[(f >> 1) + 1] = pk(l0, l1);
        }
        vacc += __shfl_xor_sync(0xffffffffu, vacc, 1);
        if (!half) g_vs[grow] = vacc + g_bvs[0];
    }

    // weights: straight bf16 copies (12 uint4 chunks per 96-elem row)
    for (int i = tid; i < 128 * 12; i += 256) {
        int row = i / 12, c = i % 12;
        *(uint4*)(smem + AW_H + row * QP * 2 + c * 16) = *(const uint4*)&g_Wh[row * 96 + c * 8];
        *(uint4*)(smem + AW_L + row * QP * 2 + c * 16) = *(const uint4*)&g_Wl[row * 96 + c * 8];
    }
    if (tid < 128) sB[tid] = g_bb[tid];
    __syncthreads();

    // ---- MMA: warp w = rows w*16..+15, all 128 outs, K=96 (6 chunks) ----
    const int w = tid >> 5, lane = tid & 31;
    const int qr = w * 16;
    const int arow = qr + (lane & 15);
    const int acol = (lane >> 4) * 8;
    const int brow = (lane & 7) + ((lane >> 4) << 3);
    const int bcol = ((lane >> 3) & 1) * 8;

    float C[16][4];
    #pragma unroll
    for (int nt = 0; nt < 16; ++nt)
        #pragma unroll
        for (int j = 0; j < 4; ++j) C[nt][j] = 0.f;

    #pragma unroll
    for (int dc = 0; dc < 6; ++dc) {
        uint32_t Ah[4], Al[4];
        unsigned aoff = (unsigned)(arow * QP + dc * 16 + acol) * 2;
        ldsm_x4(Ah, sbase + AX_H + aoff);
        ldsm_x4(Al, sbase + AX_L + aoff);
        #pragma unroll
        for (int nt2 = 0; nt2 < 8; ++nt2) {
            unsigned boff = (unsigned)((nt2 * 16 + brow) * QP + dc * 16 + bcol) * 2;
            uint32_t Bh[4], Bl[4];
            ldsm_x4(Bh, sbase + AW_H + boff);
            ldsm_x4(Bl, sbase + AW_L + boff);
            mma_bf16(C[nt2 * 2],     Ah, Bh);
            mma_bf16(C[nt2 * 2 + 1], Ah, Bh + 2);
            mma_bf16(C[nt2 * 2],     Ah, Bl);
            mma_bf16(C[nt2 * 2 + 1], Ah, Bl + 2);
            mma_bf16(C[nt2 * 2],     Al, Bh);
            mma_bf16(C[nt2 * 2 + 1], Al, Bh + 2);
        }
    }
    __syncthreads();   // all ldsm reads done; x/W smem now reusable as staging

    // ---- epilogue: bias + scale + split, stage packed bf16 in smem ----
    // staging: Qh->AX_H, Ql->AX_L, Kh->AW_H, Kl->AW_L, pitch ST_P=144B.
    // STS.32 banks: (36*row + word) covers all 32 banks per warp -> conflict-free.
    {
        const int rl = qr + (lane >> 2);
        #pragma unroll
        for (int nt = 0; nt < 16; ++nt) {
            int cb = nt * 8 + (lane & 3) * 2;
            bool isQ = (nt < 8);
            float scl = isQ ? SCQ : 1.0f;
            int cc = isQ ? cb : (cb - 64);
            char* sh = smem + (isQ ? AX_H : AW_H);
            char* sl = smem + (isQ ? AX_L : AW_L);
            float b0 = sB[cb], b1 = sB[cb + 1];
            float v00 = (C[nt][0] + b0) * scl, v01 = (C[nt][1] + b1) * scl;
            float v10 = (C[nt][2] + b0) * scl, v11 = (C[nt][3] + b1) * scl;
            __nv_bfloat16 h0, l0, h1, l1;
            bsplit(v00, h0, l0); bsplit(v01, h1, l1);
            *(unsigned*)(sh + rl * ST_P + cc * 2) = pk(h0, h1);
            *(unsigned*)(sl + rl * ST_P + cc * 2) = pk(l0, l1);
            bsplit(v10, h0, l0); bsplit(v11, h1, l1);
            *(unsigned*)(sh + (rl + 8) * ST_P + cc * 2) = pk(h0, h1);
            *(unsigned*)(sl + (rl + 8) * ST_P + cc * 2) = pk(l0, l1);
        }
    }
    __syncthreads();

    // ---- copy-out: coalesced uint4 stores (4 arrays x 4 iters/thread) ----
    {
        const int offs[4] = {AX_H, AX_L, AW_H, AW_L};
        __nv_bfloat16* dsts[4] = {g_Qh, g_Ql, g_Kh, g_Kl};
        #pragma unroll
        for (int a = 0; a < 4; ++a) {
            const char* src = smem + offs[a];
            __nv_bfloat16* dst = dsts[a];
            #pragma unroll
            for (int it = 0; it < 4; ++it) {
                int i = tid + it * 256;
                int row = i >> 3, c = i & 7;
                uint4 v = *(const uint4*)(src + row * ST_P + c * 16);
                *(uint4*)&dst[(size_t)(row0 + row) * 64 + c * 8] = v;
            }
        }
    }
}

// ---------------------------------------------------------------------------
// Kernel B: mma.sync bf16-split attention, 256 threads, 128q x 128k per CTA.
// grid = 4096: r = bid>>4, qb = (bid>>2)&3, kb = bid&3. 3 CTAs/SM.
// ---------------------------------------------------------------------------
#define QS 72
#define S_QH 0
#define S_QL (S_QH + 128 * QS * 2)          // 18432
#define S_KH (S_QL + 128 * QS * 2)          // 36864
#define S_KL (S_KH + 128 * QS * 2)          // 55296
#define S_VS (S_KL + 128 * QS * 2)          // 73728
#define B_SMEM_BYTES (S_VS + 128 * 4)       // 74240

__global__ void __launch_bounds__(256, 3) attn_mma_kernel()
{
    extern __shared__ char smem[];
    const unsigned sbase = smem_u32(smem);
    const int tid = threadIdx.x;
    const int r  = blockIdx.x >> 4;
    const int qb = (blockIdx.x >> 2) & 3;
    const int kb = blockIdx.x & 3;
    const int kbase = r * KPR;
    const int qrow0 = kbase + qb * 128;
    const int krow0 = kbase + kb * 128;

    // ---- load Q (hi/lo), K-slice (hi/lo), vsum-slice into smem ----
    {
        const uint4* Qh4 = (const uint4*)g_Qh;
        const uint4* Ql4 = (const uint4*)g_Ql;
        const uint4* Kh4 = (const uint4*)g_Kh;
        const uint4* Kl4 = (const uint4*)g_Kl;
        for (int i = tid; i < 1024; i += 256) {
            int row = i >> 3, c = i & 7;
            unsigned off = row * QS * 2 + c * 16;
            size_t gq = (size_t)(qrow0 + row) * 8 + c;
            size_t gk = (size_t)(krow0 + row) * 8 + c;
            *(uint4*)(smem + S_QH + off) = Qh4[gq];
            *(uint4*)(smem + S_QL + off) = Ql4[gq];
            *(uint4*)(smem + S_KH + off) = Kh4[gk];
            *(uint4*)(smem + S_KL + off) = Kl4[gk];
        }
        if (tid < 128)
            *(float*)(smem + S_VS + tid * 4) = g_vs[krow0 + tid];
    }
    __syncthreads();

    const int w = tid >> 5, lane = tid & 31;
    const int qr = w * 16;

    // ---- resident A fragments (Qh, Ql), 4 d-chunks ----
    uint32_t Ah[4][4], Al[4][4];
    {
        int arow = qr + (lane & 15);
        int acol = (lane >> 4) * 8;
        #pragma unroll
        for (int dc = 0; dc < 4; ++dc) {
            unsigned off = (unsigned)(arow * QS + dc * 16 + acol) * 2;
            ldsm_x4(Ah[dc], sbase + S_QH + off);
            ldsm_x4(Al[dc], sbase + S_QL + off);
        }
    }

    float se0 = 0.f, sv0 = 0.f, se1 = 0.f, sv1 = 0.f;
    const int brow = (lane & 7) + ((lane >> 4) << 3);
    const int bcol = ((lane >> 3) & 1) * 8;
    const float* vsp = (const float*)(smem + S_VS);
    const int c0off = 2 * (lane & 3);

    #pragma unroll
    for (int kt = 0; kt < 4; ++kt) {          // 32 k-cols per chunk
        float C[4][4];
        #pragma unroll
        for (int nt = 0; nt < 4; ++nt)
            #pragma unroll
            for (int j = 0; j < 4; ++j) C[nt][j] = 0.f;

        #pragma unroll
        for (int dc = 0; dc < 4; ++dc) {
            #pragma unroll
            for (int nt2 = 0; nt2 < 2; ++nt2) {
                int n0 = kt * 32 + nt2 * 16;
                unsigned off = (unsigned)((n0 + brow) * QS + dc * 16 + bcol) * 2;
                uint32_t Bh[4], Bl[4];
                ldsm_x4(Bh, sbase + S_KH + off);
                ldsm_x4(Bl, sbase + S_KL + off);
                mma_bf16(C[nt2 * 2],     Ah[dc], Bh);
                mma_bf16(C[nt2 * 2 + 1], Ah[dc], Bh + 2);
                mma_bf16(C[nt2 * 2],     Ah[dc], Bl);
                mma_bf16(C[nt2 * 2 + 1], Ah[dc], Bl + 2);
                mma_bf16(C[nt2 * 2],     Al[dc], Bh);
                mma_bf16(C[nt2 * 2 + 1], Al[dc], Bh + 2);
            }
        }

        // epilogue for this 32-k chunk (scores already in log2 units)
        #pragma unroll
        for (int nt = 0; nt < 4; ++nt) {
            int col0 = kt * 32 + nt * 8 + c0off;
            float2 vv = *(const float2*)(vsp + col0);
            float e0 = ex2(C[nt][0]);
            float e1 = ex2(C[nt][1]);
            float e2 = ex2(C[nt][2]);
            float e3 = ex2(C[nt][3]);
            se0 += e0 + e1; sv0 += e0 * vv.x + e1 * vv.y;
            se1 += e2 + e3; sv1 += e2 * vv.x + e3 * vv.y;
        }
    }

    // quad reduce, then write k-slice partials (distinct addresses, no atomics)
    #pragma unroll
    for (int o = 1; o <= 2; o <<= 1) {
        se0 += __shfl_xor_sync(0xffffffffu, se0, o);
        sv0 += __shfl_xor_sync(0xffffffffu, sv0, o);
        se1 += __shfl_xor_sync(0xffffffffu, se1, o);
        sv1 += __shfl_xor_sync(0xffffffffu, sv1, o);
    }
    if ((lane & 3) == 0) {
        int row = qrow0 + qr + (lane >> 2);
        g_part[(size_t)row * 4 + kb]       = make_float2(se0, sv0);
        g_part[(size_t)(row + 8) * 4 + kb] = make_float2(se1, sv1);
    }
}

// ---------------------------------------------------------------------------
// Finalize: merge the 4 k-slice partials per row.
// ---------------------------------------------------------------------------
__global__ void __launch_bounds__(256) finalize_kernel(float* __restrict__ out)
{
    int i = blockIdx.x * 256 + threadIdx.x;
    const float4* p = (const float4*)(g_part + (size_t)i * 4);
    float4 a = p[0], b = p[1];   // (se0,sv0,se1,sv1), (se2,sv2,se3,sv3)
    out[i] = (a.y + a.w + b.y + b.w) / (a.x + a.z + b.x + b.z);
}

// ---------------------------------------------------------------------------
// Launch
// ---------------------------------------------------------------------------
extern "C" void kernel_launch(void* const* d_in, const int* in_sizes, int n_in,
                              void* d_out, int out_size)
{
    const float* power   = (const float*)d_in[0];
    const int*   ele_idx = (const int*)  d_in[1];
    // d_in[2] = range_indices (unused by reference)
    const int*   azi_idx = (const int*)  d_in[3];
    const float* ele_tab = (const float*)d_in[4];
    const float* azi_tab = (const float*)d_in[5];
    const float* Wq      = (const float*)d_in[6];
    const float* bq      = (const float*)d_in[7];
    const float* Wk      = (const float*)d_in[8];
    const float* bk      = (const float*)d_in[9];
    const float* Wv      = (const float*)d_in[10];
    const float* bv      = (const float*)d_in[11];
    float* out = (float*)d_out;

    cudaFuncSetAttribute(qkv_mma_kernel, cudaFuncAttributeMaxDynamicSharedMemorySize, A_SMEM_BYTES);
    cudaFuncSetAttribute(attn_mma_kernel, cudaFuncAttributeMaxDynamicSharedMemorySize, B_SMEM_BYTES);

    prep_kernel<<<1, 128>>>(Wq, bq, Wk, bk, Wv, bv);
    qkv_mma_kernel<<<NROWS / 128, 256, A_SMEM_BYTES>>>(
        power, ele_idx, azi_idx, ele_tab, azi_tab);
    attn_mma_kernel<<<NUM_RANGES * 16, 256, B_SMEM_BYTES>>>();
    finalize_kernel<<<NROWS / 256, 256>>>(out);
}

// round 11
// speedup vs baseline: 1.7070x; 1.1133x over previous
#include <cuda_runtime.h>
#include <cuda_fp16.h>
#include <math.h>
#include <stdint.h>

#define NUM_RANGES 256
#define KPR 512
#define DOPPLER 64
#define EMBED 16
#define IN_DIM 96
#define NROWS (NUM_RANGES * KPR)   // 131072

// Scratch (static device allocations are permitted)
__device__ __half g_Qf[NROWS * 64];         // fp16 Q, pre-scaled by log2(e)/8
__device__ __half g_Kh[NROWS * 64];         // fp16 hi part of K
__device__ __half g_Kl[NROWS * 64];         // fp16 lo (residual) part of K
__device__ float g_vs[NROWS];
__device__ float2 g_part[NROWS * 4];        // per-(row, k-slice) partial (se, sv)
__device__ __half g_Wh[128 * 96];           // pre-split weights (rows 0..63 Wq, 64..127 Wk)
__device__ __half g_Wl[128 * 96];
__device__ float g_wvs[96];
__device__ float g_bb[128];
__device__ float g_bvs[1];

// ---------------- mma.sync / ldmatrix helpers (sm_80+ PTX, sm_103-safe) -----
__device__ __forceinline__ unsigned smem_u32(const void* p) {
    unsigned a;
    asm("{ .reg .u64 t; cvta.to.shared.u64 t, %1; cvt.u32.u64 %0, t; }" : "=r"(a) : "l"(p));
    return a;
}
__device__ __forceinline__ void ldsm_x4(uint32_t* r, unsigned addr) {
    asm volatile("ldmatrix.sync.aligned.m8n8.x4.shared.b16 {%0,%1,%2,%3}, [%4];"
                 : "=r"(r[0]), "=r"(r[1]), "=r"(r[2]), "=r"(r[3]) : "r"(addr));
}
__device__ __forceinline__ void mma_f16(float* c, const uint32_t* a, const uint32_t* b) {
    asm volatile("mma.sync.aligned.m16n8k16.row.col.f32.f16.f16.f32 "
                 "{%0,%1,%2,%3}, {%4,%5,%6,%7}, {%8,%9}, {%0,%1,%2,%3};"
                 : "+f"(c[0]), "+f"(c[1]), "+f"(c[2]), "+f"(c[3])
                 : "r"(a[0]), "r"(a[1]), "r"(a[2]), "r"(a[3]), "r"(b[0]), "r"(b[1]));
}
__device__ __forceinline__ float ex2(float x) {
    float y; asm("ex2.approx.f32 %0, %1;" : "=f"(y) : "f"(x)); return y;
}
__device__ __forceinline__ void hsplit(float v, __half& h, __half& l) {
    h = __float2half_rn(v);
    l = __float2half_rn(v - __half2float(h));
}
__device__ __forceinline__ unsigned pk(__half a, __half b) {
    return (unsigned)__half_as_ushort(a) | ((unsigned)__half_as_ushort(b) << 16);
}

#define SCQ 0.1803368801111244f   // log2(e) / sqrt(64)

// ---------------------------------------------------------------------------
// Prep kernel: one-time weight split (fp16 hi/lo) + wv colsums + bias staging.
// ---------------------------------------------------------------------------
__global__ void __launch_bounds__(128) prep_kernel(
    const float* __restrict__ Wq, const float* __restrict__ bq,
    const float* __restrict__ Wk, const float* __restrict__ bk,
    const float* __restrict__ Wv, const float* __restrict__ bv)
{
    const int tid = threadIdx.x;
    for (int i = tid; i < 64 * 96; i += 128) {
        int d = i / 96, f = i % 96;
        __half h, l;
        hsplit(Wq[i], h, l); g_Wh[d * 96 + f] = h;        g_Wl[d * 96 + f] = l;
        hsplit(Wk[i], h, l); g_Wh[(64 + d) * 96 + f] = h; g_Wl[(64 + d) * 96 + f] = l;
    }
    if (tid < 96) {
        float s = 0.f;
        #pragma unroll 8
        for (int d = 0; d < 64; ++d) s += Wv[d * 96 + tid];
        g_wvs[tid] = s;
    }
    if (tid < 64) { g_bb[tid] = bq[tid]; g_bb[64 + tid] = bk[tid]; }
    if (tid == 0) {
        float s = 0.f;
        #pragma unroll 8
        for (int d = 0; d < 64; ++d) s += bv[d];
        g_bvs[0] = s;
    }
}

// ---------------------------------------------------------------------------
// Kernel A: fused gather + QK projection via mma.sync (fp16 3-term, err ~2^-22).
// CTA = 128 rows x 128 outs x 96, 256 thr, 2 CTAs/SM.
// Epilogue: Q -> fp16 single (xSCQ), K -> fp16 hi/lo. 3 output arrays.
// ---------------------------------------------------------------------------
#define QP 104
#define ST_P 144                            // staging row pitch (bytes)
#define AX_H 0
#define AX_L (AX_H + 128 * QP * 2)          // 26624
#define AW_H (AX_L + 128 * QP * 2)          // 53248
#define AW_L (AW_H + 128 * QP * 2)          // 79872
#define A_BB (AW_L + 128 * QP * 2)          // 106496  float[128]
#define A_SMEM_BYTES (A_BB + 128 * 4)       // 107008

__global__ void __launch_bounds__(256, 2) qkv_mma_kernel(
    const float* __restrict__ power, const int* __restrict__ ele_idx,
    const int* __restrict__ azi_idx, const float* __restrict__ ele_tab,
    const float* __restrict__ azi_tab)
{
    extern __shared__ char smem[];
    const unsigned sbase = smem_u32(smem);
    __half* xh = (__half*)(smem + AX_H);
    __half* xl = (__half*)(smem + AX_L);
    float* sB = (float*)(smem + A_BB);

    const int tid  = threadIdx.x;
    const int row0 = blockIdx.x * 128;

    // ---- fused gather + fp16 split + inline vsum (2 threads per row) ----
    {
        const int row = tid >> 1, half = tid & 1;
        const int grow = row0 + row;
        unsigned* xhrow = (unsigned*)(xh + row * QP);
        unsigned* xlrow = (unsigned*)(xl + row * QP);
        float vacc = 0.f;

        const float4* pv = (const float4*)(power + (size_t)grow * 64 + half * 32);
        #pragma unroll
        for (int u = 0; u < 8; ++u) {
            float4 v = pv[u];
            int f = half * 32 + u * 4;
            vacc += v.x * g_wvs[f]     + v.y * g_wvs[f + 1]
                  + v.z * g_wvs[f + 2] + v.w * g_wvs[f + 3];
            __half h0, l0, h1, l1;
            hsplit(v.x, h0, l0); hsplit(v.y, h1, l1);
            xhrow[f >> 1] = pk(h0, h1); xlrow[f >> 1] = pk(l0, l1);
            hsplit(v.z, h0, l0); hsplit(v.w, h1, l1);
            xhrow[(f >> 1) + 1] = pk(h0, h1); xlrow[(f >> 1) + 1] = pk(l0, l1);
        }
        const int eidx = half ? azi_idx[grow] : ele_idx[grow];
        const float4* ev = (const float4*)((half ? azi_tab : ele_tab) + (size_t)eidx * 16);
        const int fbase = 64 + half * 16;
        #pragma unroll
        for (int u = 0; u < 4; ++u) {
            float4 v = ev[u];
            int f = fbase + u * 4;
            vacc += v.x * g_wvs[f]     + v.y * g_wvs[f + 1]
                  + v.z * g_wvs[f + 2] + v.w * g_wvs[f + 3];
            __half h0, l0, h1, l1;
            hsplit(v.x, h0, l0); hsplit(v.y, h1, l1);
            xhrow[f >> 1] = pk(h0, h1); xlrow[f >> 1] = pk(l0, l1);
            hsplit(v.z, h0, l0); hsplit(v.w, h1, l1);
            xhrow[(f >> 1) + 1] = pk(h0, h1); xlrow[(f >> 1) + 1] = pk(l0, l1);
        }
        vacc += __shfl_xor_sync(0xffffffffu, vacc, 1);
        if (!half) g_vs[grow] = vacc + g_bvs[0];
    }

    // weights: straight fp16 copies (12 uint4 chunks per 96-elem row)
    for (int i = tid; i < 128 * 12; i += 256) {
        int row = i / 12, c = i % 12;
        *(uint4*)(smem + AW_H + row * QP * 2 + c * 16) = *(const uint4*)&g_Wh[row * 96 + c * 8];
        *(uint4*)(smem + AW_L + row * QP * 2 + c * 16) = *(const uint4*)&g_Wl[row * 96 + c * 8];
    }
    if (tid < 128) sB[tid] = g_bb[tid];
    __syncthreads();

    // ---- MMA: warp w = rows w*16..+15, all 128 outs, K=96 (6 chunks) ----
    const int w = tid >> 5, lane = tid & 31;
    const int qr = w * 16;
    const int arow = qr + (lane & 15);
    const int acol = (lane >> 4) * 8;
    const int brow = (lane & 7) + ((lane >> 4) << 3);
    const int bcol = ((lane >> 3) & 1) * 8;

    float C[16][4];
    #pragma unroll
    for (int nt = 0; nt < 16; ++nt)
        #pragma unroll
        for (int j = 0; j < 4; ++j) C[nt][j] = 0.f;

    #pragma unroll
    for (int dc = 0; dc < 6; ++dc) {
        uint32_t Ah[4], Al[4];
        unsigned aoff = (unsigned)(arow * QP + dc * 16 + acol) * 2;
        ldsm_x4(Ah, sbase + AX_H + aoff);
        ldsm_x4(Al, sbase + AX_L + aoff);
        #pragma unroll
        for (int nt2 = 0; nt2 < 8; ++nt2) {
            unsigned boff = (unsigned)((nt2 * 16 + brow) * QP + dc * 16 + bcol) * 2;
            uint32_t Bh[4], Bl[4];
            ldsm_x4(Bh, sbase + AW_H + boff);
            ldsm_x4(Bl, sbase + AW_L + boff);
            mma_f16(C[nt2 * 2],     Ah, Bh);
            mma_f16(C[nt2 * 2 + 1], Ah, Bh + 2);
            mma_f16(C[nt2 * 2],     Ah, Bl);
            mma_f16(C[nt2 * 2 + 1], Ah, Bl + 2);
            mma_f16(C[nt2 * 2],     Al, Bh);
            mma_f16(C[nt2 * 2 + 1], Al, Bh + 2);
        }
    }
    __syncthreads();   // all ldsm reads done; x/W smem now reusable as staging

    // ---- epilogue: bias + scale; Q -> fp16 single, K -> fp16 hi/lo ----
    // staging: Qf->AX_H, Kh->AX_L, Kl->AW_H, pitch ST_P=144B (conflict-free).
    {
        const int rl = qr + (lane >> 2);
        #pragma unroll
        for (int nt = 0; nt < 16; ++nt) {
            int cb = nt * 8 + (lane & 3) * 2;
            bool isQ = (nt < 8);
            float b0 = sB[cb], b1 = sB[cb + 1];
            if (isQ) {
                char* sq = smem + AX_H;
                float v00 = (C[nt][0] + b0) * SCQ, v01 = (C[nt][1] + b1) * SCQ;
                float v10 = (C[nt][2] + b0) * SCQ, v11 = (C[nt][3] + b1) * SCQ;
                *(unsigned*)(sq + rl * ST_P + cb * 2) =
                    pk(__float2half_rn(v00), __float2half_rn(v01));
                *(unsigned*)(sq + (rl + 8) * ST_P + cb * 2) =
                    pk(__float2half_rn(v10), __float2half_rn(v11));
            } else {
                int cc = cb - 64;
                char* sh = smem + AX_L;
                char* sl = smem + AW_H;
                float v00 = C[nt][0] + b0, v01 = C[nt][1] + b1;
                float v10 = C[nt][2] + b0, v11 = C[nt][3] + b1;
                __half h0, l0, h1, l1;
                hsplit(v00, h0, l0); hsplit(v01, h1, l1);
                *(unsigned*)(sh + rl * ST_P + cc * 2) = pk(h0, h1);
                *(unsigned*)(sl + rl * ST_P + cc * 2) = pk(l0, l1);
                hsplit(v10, h0, l0); hsplit(v11, h1, l1);
                *(unsigned*)(sh + (rl + 8) * ST_P + cc * 2) = pk(h0, h1);
                *(unsigned*)(sl + (rl + 8) * ST_P + cc * 2) = pk(l0, l1);
            }
        }
    }
    __syncthreads();

    // ---- copy-out: coalesced uint4 stores (3 arrays x 4 iters/thread) ----
    {
        const int offs[3] = {AX_H, AX_L, AW_H};
        __half* dsts[3] = {g_Qf, g_Kh, g_Kl};
        #pragma unroll
        for (int a = 0; a < 3; ++a) {
            const char* src = smem + offs[a];
            __half* dst = dsts[a];
            #pragma unroll
            for (int it = 0; it < 4; ++it) {
                int i = tid + it * 256;
                int row = i >> 3, c = i & 7;
                uint4 v = *(const uint4*)(src + row * ST_P + c * 16);
                *(uint4*)&dst[(size_t)(row0 + row) * 64 + c * 8] = v;
            }
        }
    }
}

// ---------------------------------------------------------------------------
// Kernel B: mma.sync 2-product attention: scores = Qf*Kh + Qf*Kl.
// 256 threads, 128q x 128k per CTA, grid = 4096, 3 CTAs/SM.
// ---------------------------------------------------------------------------
#define QS 72
#define S_QF 0
#define S_KH (S_QF + 128 * QS * 2)          // 18432
#define S_KL (S_KH + 128 * QS * 2)          // 36864
#define S_VS (S_KL + 128 * QS * 2)          // 55296
#define B_SMEM_BYTES (S_VS + 128 * 4)       // 55808

__global__ void __launch_bounds__(256, 3) attn_mma_kernel()
{
    extern __shared__ char smem[];
    const unsigned sbase = smem_u32(smem);
    const int tid = threadIdx.x;
    const int r  = blockIdx.x >> 4;
    const int qb = (blockIdx.x >> 2) & 3;
    const int kb = blockIdx.x & 3;
    const int kbase = r * KPR;
    const int qrow0 = kbase + qb * 128;
    const int krow0 = kbase + kb * 128;

    // ---- load Qf, K-slice (hi/lo), vsum-slice into smem ----
    {
        const uint4* Qf4 = (const uint4*)g_Qf;
        const uint4* Kh4 = (const uint4*)g_Kh;
        const uint4* Kl4 = (const uint4*)g_Kl;
        for (int i = tid; i < 1024; i += 256) {
            int row = i >> 3, c = i & 7;
            unsigned off = row * QS * 2 + c * 16;
            size_t gq = (size_t)(qrow0 + row) * 8 + c;
            size_t gk = (size_t)(krow0 + row) * 8 + c;
            *(uint4*)(smem + S_QF + off) = Qf4[gq];
            *(uint4*)(smem + S_KH + off) = Kh4[gk];
            *(uint4*)(smem + S_KL + off) = Kl4[gk];
        }
        if (tid < 128)
            *(float*)(smem + S_VS + tid * 4) = g_vs[krow0 + tid];
    }
    __syncthreads();

    const int w = tid >> 5, lane = tid & 31;
    const int qr = w * 16;

    // ---- resident A fragments (Qf), 4 d-chunks ----
    uint32_t Af[4][4];
    {
        int arow = qr + (lane & 15);
        int acol = (lane >> 4) * 8;
        #pragma unroll
        for (int dc = 0; dc < 4; ++dc) {
            unsigned off = (unsigned)(arow * QS + dc * 16 + acol) * 2;
            ldsm_x4(Af[dc], sbase + S_QF + off);
        }
    }

    float se0 = 0.f, sv0 = 0.f, se1 = 0.f, sv1 = 0.f;
    const int brow = (lane & 7) + ((lane >> 4) << 3);
    const int bcol = ((lane >> 3) & 1) * 8;
    const float* vsp = (const float*)(smem + S_VS);
    const int c0off = 2 * (lane & 3);

    #pragma unroll
    for (int kt = 0; kt < 4; ++kt) {          // 32 k-cols per chunk
        float C[4][4];
        #pragma unroll
        for (int nt = 0; nt < 4; ++nt)
            #pragma unroll
            for (int j = 0; j < 4; ++j) C[nt][j] = 0.f;

        #pragma unroll
        for (int dc = 0; dc < 4; ++dc) {
            #pragma unroll
            for (int nt2 = 0; nt2 < 2; ++nt2) {
                int n0 = kt * 32 + nt2 * 16;
                unsigned off = (unsigned)((n0 + brow) * QS + dc * 16 + bcol) * 2;
                uint32_t Bh[4], Bl[4];
                ldsm_x4(Bh, sbase + S_KH + off);
                ldsm_x4(Bl, sbase + S_KL + off);
                mma_f16(C[nt2 * 2],     Af[dc], Bh);
                mma_f16(C[nt2 * 2 + 1], Af[dc], Bh + 2);
                mma_f16(C[nt2 * 2],     Af[dc], Bl);
                mma_f16(C[nt2 * 2 + 1], Af[dc], Bl + 2);
            }
        }

        // epilogue for this 32-k chunk (scores already in log2 units)
        #pragma unroll
        for (int nt = 0; nt < 4; ++nt) {
            int col0 = kt * 32 + nt * 8 + c0off;
            float2 vv = *(const float2*)(vsp + col0);
            float e0 = ex2(C[nt][0]);
            float e1 = ex2(C[nt][1]);
            float e2 = ex2(C[nt][2]);
            float e3 = ex2(C[nt][3]);
            se0 += e0 + e1; sv0 += e0 * vv.x + e1 * vv.y;
            se1 += e2 + e3; sv1 += e2 * vv.x + e3 * vv.y;
        }
    }

    // quad reduce, then write k-slice partials (distinct addresses, no atomics)
    #pragma unroll
    for (int o = 1; o <= 2; o <<= 1) {
        se0 += __shfl_xor_sync(0xffffffffu, se0, o);
        sv0 += __shfl_xor_sync(0xffffffffu, sv0, o);
        se1 += __shfl_xor_sync(0xffffffffu, se1, o);
        sv1 += __shfl_xor_sync(0xffffffffu, sv1, o);
    }
    if ((lane & 3) == 0) {
        int row = qrow0 + qr + (lane >> 2);
        g_part[(size_t)row * 4 + kb]       = make_float2(se0, sv0);
        g_part[(size_t)(row + 8) * 4 + kb] = make_float2(se1, sv1);
    }
}

// ---------------------------------------------------------------------------
// Finalize: merge the 4 k-slice partials per row.
// ---------------------------------------------------------------------------
__global__ void __launch_bounds__(256) finalize_kernel(float* __restrict__ out)
{
    int i = blockIdx.x * 256 + threadIdx.x;
    const float4* p = (const float4*)(g_part + (size_t)i * 4);
    float4 a = p[0], b = p[1];   // (se0,sv0,se1,sv1), (se2,sv2,se3,sv3)
    out[i] = (a.y + a.w + b.y + b.w) / (a.x + a.z + b.x + b.z);
}

// ---------------------------------------------------------------------------
// Launch
// ---------------------------------------------------------------------------
extern "C" void kernel_launch(void* const* d_in, const int* in_sizes, int n_in,
                              void* d_out, int out_size)
{
    const float* power   = (const float*)d_in[0];
    const int*   ele_idx = (const int*)  d_in[1];
    // d_in[2] = range_indices (unused by reference)
    const int*   azi_idx = (const int*)  d_in[3];
    const float* ele_tab = (const float*)d_in[4];
    const float* azi_tab = (const float*)d_in[5];
    const float* Wq      = (const float*)d_in[6];
    const float* bq      = (const float*)d_in[7];
    const float* Wk      = (const float*)d_in[8];
    const float* bk      = (const float*)d_in[9];
    const float* Wv      = (const float*)d_in[10];
    const float* bv      = (const float*)d_in[11];
    float* out = (float*)d_out;

    cudaFuncSetAttribute(qkv_mma_kernel, cudaFuncAttributeMaxDynamicSharedMemorySize, A_SMEM_BYTES);
    cudaFuncSetAttribute(attn_mma_kernel, cudaFuncAttributeMaxDynamicSharedMemorySize, B_SMEM_BYTES);

    prep_kernel<<<1, 128>>>(Wq, bq, Wk, bk, Wv, bv);
    qkv_mma_kernel<<<NROWS / 128, 256, A_SMEM_BYTES>>>(
        power, ele_idx, azi_idx, ele_tab, azi_tab);
    attn_mma_kernel<<<NUM_RANGES * 16, 256, B_SMEM_BYTES>>>();
    finalize_kernel<<<NROWS / 256, 256>>>(out);
}

// round 12
// speedup vs baseline: 2.3607x; 1.3830x over previous
#include <cuda_runtime.h>
#include <cuda_fp16.h>
#include <math.h>
#include <stdint.h>

#define NUM_RANGES 256
#define KPR 512
#define DOPPLER 64
#define EMBED 16
#define IN_DIM 96
#define NROWS (NUM_RANGES * KPR)   // 131072

// Scratch (static device allocations are permitted)
__device__ __half g_Qf[NROWS * 64];         // fp16 Q, pre-scaled by log2(e)/8
__device__ __half g_Kf[NROWS * 64];         // fp16 K
__device__ float g_vs[NROWS];
__device__ float2 g_part[NROWS * 4];        // per-(row, k-slice) partial (se, sv)
__device__ __half g_Wh[128 * 96];           // pre-split weights (rows 0..63 Wq, 64..127 Wk)
__device__ __half g_Wl[128 * 96];
__device__ float g_wvs[96];
__device__ float g_bb[128];
__device__ float g_bvs[1];

// ---------------- mma.sync / ldmatrix helpers (sm_80+ PTX, sm_103-safe) -----
__device__ __forceinline__ unsigned smem_u32(const void* p) {
    unsigned a;
    asm("{ .reg .u64 t; cvta.to.shared.u64 t, %1; cvt.u32.u64 %0, t; }" : "=r"(a) : "l"(p));
    return a;
}
__device__ __forceinline__ void ldsm_x4(uint32_t* r, unsigned addr) {
    asm volatile("ldmatrix.sync.aligned.m8n8.x4.shared.b16 {%0,%1,%2,%3}, [%4];"
                 : "=r"(r[0]), "=r"(r[1]), "=r"(r[2]), "=r"(r[3]) : "r"(addr));
}
__device__ __forceinline__ void mma_f16(float* c, const uint32_t* a, const uint32_t* b) {
    asm volatile("mma.sync.aligned.m16n8k16.row.col.f32.f16.f16.f32 "
                 "{%0,%1,%2,%3}, {%4,%5,%6,%7}, {%8,%9}, {%0,%1,%2,%3};"
                 : "+f"(c[0]), "+f"(c[1]), "+f"(c[2]), "+f"(c[3])
                 : "r"(a[0]), "r"(a[1]), "r"(a[2]), "r"(a[3]), "r"(b[0]), "r"(b[1]));
}
__device__ __forceinline__ float ex2(float x) {
    float y; asm("ex2.approx.f32 %0, %1;" : "=f"(y) : "f"(x)); return y;
}
__device__ __forceinline__ void hsplit(float v, __half& h, __half& l) {
    h = __float2half_rn(v);
    l = __float2half_rn(v - __half2float(h));
}
__device__ __forceinline__ unsigned pk(__half a, __half b) {
    return (unsigned)__half_as_ushort(a) | ((unsigned)__half_as_ushort(b) << 16);
}

#define SCQ 0.1803368801111244f   // log2(e) / sqrt(64)

// ---------------------------------------------------------------------------
// Prep kernel: one-time weight split (fp16 hi/lo) + wv colsums + bias staging.
// ---------------------------------------------------------------------------
__global__ void __launch_bounds__(128) prep_kernel(
    const float* __restrict__ Wq, const float* __restrict__ bq,
    const float* __restrict__ Wk, const float* __restrict__ bk,
    const float* __restrict__ Wv, const float* __restrict__ bv)
{
    const int tid = threadIdx.x;
    for (int i = tid; i < 64 * 96; i += 128) {
        int d = i / 96, f = i % 96;
        __half h, l;
        hsplit(Wq[i], h, l); g_Wh[d * 96 + f] = h;        g_Wl[d * 96 + f] = l;
        hsplit(Wk[i], h, l); g_Wh[(64 + d) * 96 + f] = h; g_Wl[(64 + d) * 96 + f] = l;
    }
    if (tid < 96) {
        float s = 0.f;
        #pragma unroll 8
        for (int d = 0; d < 64; ++d) s += Wv[d * 96 + tid];
        g_wvs[tid] = s;
    }
    if (tid < 64) { g_bb[tid] = bq[tid]; g_bb[64 + tid] = bk[tid]; }
    if (tid == 0) {
        float s = 0.f;
        #pragma unroll 8
        for (int d = 0; d < 64; ++d) s += bv[d];
        g_bvs[0] = s;
    }
}

// ---------------------------------------------------------------------------
// Kernel A: fused gather + QK projection via mma.sync.
// x fp16-single; W fp16 hi/lo -> 2-term product (x*Wh + x*Wl).
// CTA = 128 rows x 128 outs x 96, 256 thr, 2 CTAs/SM.
// Epilogue: Q -> fp16 (xSCQ), K -> fp16. 2 output arrays.
// ---------------------------------------------------------------------------
#define QP 104
#define ST_P 144                            // staging row pitch (bytes)
#define AX   0
#define AW_H (AX + 128 * QP * 2)            // 26624
#define AW_L (AW_H + 128 * QP * 2)          // 53248
#define A_BB (AW_L + 128 * QP * 2)          // 79872  float[128]
#define A_SMEM_BYTES (A_BB + 128 * 4)       // 80384

__global__ void __launch_bounds__(256, 2) qkv_mma_kernel(
    const float* __restrict__ power, const int* __restrict__ ele_idx,
    const int* __restrict__ azi_idx, const float* __restrict__ ele_tab,
    const float* __restrict__ azi_tab)
{
    extern __shared__ char smem[];
    const unsigned sbase = smem_u32(smem);
    __half* xf = (__half*)(smem + AX);
    float* sB = (float*)(smem + A_BB);

    const int tid  = threadIdx.x;
    const int row0 = blockIdx.x * 128;

    // ---- fused gather + fp16 convert + inline vsum (2 threads per row) ----
    {
        const int row = tid >> 1, half = tid & 1;
        const int grow = row0 + row;
        unsigned* xrow = (unsigned*)(xf + row * QP);
        float vacc = 0.f;

        const float4* pv = (const float4*)(power + (size_t)grow * 64 + half * 32);
        #pragma unroll
        for (int u = 0; u < 8; ++u) {
            float4 v = pv[u];
            int f = half * 32 + u * 4;
            vacc += v.x * g_wvs[f]     + v.y * g_wvs[f + 1]
                  + v.z * g_wvs[f + 2] + v.w * g_wvs[f + 3];
            xrow[f >> 1]       = pk(__float2half_rn(v.x), __float2half_rn(v.y));
            xrow[(f >> 1) + 1] = pk(__float2half_rn(v.z), __float2half_rn(v.w));
        }
        const int eidx = half ? azi_idx[grow] : ele_idx[grow];
        const float4* ev = (const float4*)((half ? azi_tab : ele_tab) + (size_t)eidx * 16);
        const int fbase = 64 + half * 16;
        #pragma unroll
        for (int u = 0; u < 4; ++u) {
            float4 v = ev[u];
            int f = fbase + u * 4;
            vacc += v.x * g_wvs[f]     + v.y * g_wvs[f + 1]
                  + v.z * g_wvs[f + 2] + v.w * g_wvs[f + 3];
            xrow[f >> 1]       = pk(__float2half_rn(v.x), __float2half_rn(v.y));
            xrow[(f >> 1) + 1] = pk(__float2half_rn(v.z), __float2half_rn(v.w));
        }
        vacc += __shfl_xor_sync(0xffffffffu, vacc, 1);
        if (!half) g_vs[grow] = vacc + g_bvs[0];
    }

    // weights: straight fp16 copies (12 uint4 chunks per 96-elem row)
    for (int i = tid; i < 128 * 12; i += 256) {
        int row = i / 12, c = i % 12;
        *(uint4*)(smem + AW_H + row * QP * 2 + c * 16) = *(const uint4*)&g_Wh[row * 96 + c * 8];
        *(uint4*)(smem + AW_L + row * QP * 2 + c * 16) = *(const uint4*)&g_Wl[row * 96 + c * 8];
    }
    if (tid < 128) sB[tid] = g_bb[tid];
    __syncthreads();

    // ---- MMA: warp w = rows w*16..+15, all 128 outs, K=96 (6 chunks) ----
    const int w = tid >> 5, lane = tid & 31;
    const int qr = w * 16;
    const int arow = qr + (lane & 15);
    const int acol = (lane >> 4) * 8;
    const int brow = (lane & 7) + ((lane >> 4) << 3);
    const int bcol = ((lane >> 3) & 1) * 8;

    float C[16][4];
    #pragma unroll
    for (int nt = 0; nt < 16; ++nt)
        #pragma unroll
        for (int j = 0; j < 4; ++j) C[nt][j] = 0.f;

    #pragma unroll
    for (int dc = 0; dc < 6; ++dc) {
        uint32_t Af[4];
        unsigned aoff = (unsigned)(arow * QP + dc * 16 + acol) * 2;
        ldsm_x4(Af, sbase + AX + aoff);
        #pragma unroll
        for (int nt2 = 0; nt2 < 8; ++nt2) {
            unsigned boff = (unsigned)((nt2 * 16 + brow) * QP + dc * 16 + bcol) * 2;
            uint32_t Bh[4], Bl[4];
            ldsm_x4(Bh, sbase + AW_H + boff);
            ldsm_x4(Bl, sbase + AW_L + boff);
            mma_f16(C[nt2 * 2],     Af, Bh);
            mma_f16(C[nt2 * 2 + 1], Af, Bh + 2);
            mma_f16(C[nt2 * 2],     Af, Bl);
            mma_f16(C[nt2 * 2 + 1], Af, Bl + 2);
        }
    }
    __syncthreads();   // all ldsm reads done; smem now reusable as staging

    // ---- epilogue: bias + scale; Q,K -> fp16 single; stage in smem ----
    // staging: Qf->AX, Kf->AW_H, pitch ST_P=144B (conflict-free STS.32).
    {
        const int rl = qr + (lane >> 2);
        #pragma unroll
        for (int nt = 0; nt < 16; ++nt) {
            int cb = nt * 8 + (lane & 3) * 2;
            bool isQ = (nt < 8);
            float scl = isQ ? SCQ : 1.0f;
            int cc = isQ ? cb : (cb - 64);
            char* st = smem + (isQ ? AX : AW_H);
            float b0 = sB[cb], b1 = sB[cb + 1];
            float v00 = (C[nt][0] + b0) * scl, v01 = (C[nt][1] + b1) * scl;
            float v10 = (C[nt][2] + b0) * scl, v11 = (C[nt][3] + b1) * scl;
            *(unsigned*)(st + rl * ST_P + cc * 2) =
                pk(__float2half_rn(v00), __float2half_rn(v01));
            *(unsigned*)(st + (rl + 8) * ST_P + cc * 2) =
                pk(__float2half_rn(v10), __float2half_rn(v11));
        }
    }
    __syncthreads();

    // ---- copy-out: coalesced uint4 stores (2 arrays x 4 iters/thread) ----
    {
        const int offs[2] = {AX, AW_H};
        __half* dsts[2] = {g_Qf, g_Kf};
        #pragma unroll
        for (int a = 0; a < 2; ++a) {
            const char* src = smem + offs[a];
            __half* dst = dsts[a];
            #pragma unroll
            for (int it = 0; it < 4; ++it) {
                int i = tid + it * 256;
                int row = i >> 3, c = i & 7;
                uint4 v = *(const uint4*)(src + row * ST_P + c * 16);
                *(uint4*)&dst[(size_t)(row0 + row) * 64 + c * 8] = v;
            }
        }
    }
}

// ---------------------------------------------------------------------------
// Kernel B: mma.sync single-product attention: scores = Qf*Kf.
// 256 threads, 128q x 128k per CTA, grid = 4096, 4 CTAs/SM.
// ---------------------------------------------------------------------------
#define QS 72
#define S_QF 0
#define S_KF (S_QF + 128 * QS * 2)          // 18432
#define S_VS (S_KF + 128 * QS * 2)          // 36864
#define B_SMEM_BYTES (S_VS + 128 * 4)       // 37376

__global__ void __launch_bounds__(256, 4) attn_mma_kernel()
{
    extern __shared__ char smem[];
    const unsigned sbase = smem_u32(smem);
    const int tid = threadIdx.x;
    const int r  = blockIdx.x >> 4;
    const int qb = (blockIdx.x >> 2) & 3;
    const int kb = blockIdx.x & 3;
    const int kbase = r * KPR;
    const int qrow0 = kbase + qb * 128;
    const int krow0 = kbase + kb * 128;

    // ---- load Qf, Kf-slice, vsum-slice into smem ----
    {
        const uint4* Qf4 = (const uint4*)g_Qf;
        const uint4* Kf4 = (const uint4*)g_Kf;
        for (int i = tid; i < 1024; i += 256) {
            int row = i >> 3, c = i & 7;
            unsigned off = row * QS * 2 + c * 16;
            *(uint4*)(smem + S_QF + off) = Qf4[(size_t)(qrow0 + row) * 8 + c];
            *(uint4*)(smem + S_KF + off) = Kf4[(size_t)(krow0 + row) * 8 + c];
        }
        if (tid < 128)
            *(float*)(smem + S_VS + tid * 4) = g_vs[krow0 + tid];
    }
    __syncthreads();

    const int w = tid >> 5, lane = tid & 31;
    const int qr = w * 16;

    // ---- resident A fragments (Qf), 4 d-chunks ----
    uint32_t Af[4][4];
    {
        int arow = qr + (lane & 15);
        int acol = (lane >> 4) * 8;
        #pragma unroll
        for (int dc = 0; dc < 4; ++dc) {
            unsigned off = (unsigned)(arow * QS + dc * 16 + acol) * 2;
            ldsm_x4(Af[dc], sbase + S_QF + off);
        }
    }

    float se0 = 0.f, sv0 = 0.f, se1 = 0.f, sv1 = 0.f;
    const int brow = (lane & 7) + ((lane >> 4) << 3);
    const int bcol = ((lane >> 3) & 1) * 8;
    const float* vsp = (const float*)(smem + S_VS);
    const int c0off = 2 * (lane & 3);

    #pragma unroll
    for (int kt = 0; kt < 4; ++kt) {          // 32 k-cols per chunk
        float C[4][4];
        #pragma unroll
        for (int nt = 0; nt < 4; ++nt)
            #pragma unroll
            for (int j = 0; j < 4; ++j) C[nt][j] = 0.f;

        #pragma unroll
        for (int dc = 0; dc < 4; ++dc) {
            #pragma unroll
            for (int nt2 = 0; nt2 < 2; ++nt2) {
                int n0 = kt * 32 + nt2 * 16;
                unsigned off = (unsigned)((n0 + brow) * QS + dc * 16 + bcol) * 2;
                uint32_t Bf[4];
                ldsm_x4(Bf, sbase + S_KF + off);
                mma_f16(C[nt2 * 2],     Af[dc], Bf);
                mma_f16(C[nt2 * 2 + 1], Af[dc], Bf + 2);
            }
        }

        // epilogue for this 32-k chunk (scores already in log2 units)
        #pragma unroll
        for (int nt = 0; nt < 4; ++nt) {
            int col0 = kt * 32 + nt * 8 + c0off;
            float2 vv = *(const float2*)(vsp + col0);
            float e0 = ex2(C[nt][0]);
            float e1 = ex2(C[nt][1]);
            float e2 = ex2(C[nt][2]);
            float e3 = ex2(C[nt][3]);
            se0 += e0 + e1; sv0 += e0 * vv.x + e1 * vv.y;
            se1 += e2 + e3; sv1 += e2 * vv.x + e3 * vv.y;
        }
    }

    // quad reduce, then write k-slice partials (distinct addresses, no atomics)
    #pragma unroll
    for (int o = 1; o <= 2; o <<= 1) {
        se0 += __shfl_xor_sync(0xffffffffu, se0, o);
        sv0 += __shfl_xor_sync(0xffffffffu, sv0, o);
        se1 += __shfl_xor_sync(0xffffffffu, se1, o);
        sv1 += __shfl_xor_sync(0xffffffffu, sv1, o);
    }
    if ((lane & 3) == 0) {
        int row = qrow0 + qr + (lane >> 2);
        g_part[(size_t)row * 4 + kb]       = make_float2(se0, sv0);
        g_part[(size_t)(row + 8) * 4 + kb] = make_float2(se1, sv1);
    }
}

// ---------------------------------------------------------------------------
// Finalize: merge the 4 k-slice partials per row.
// ---------------------------------------------------------------------------
__global__ void __launch_bounds__(256) finalize_kernel(float* __restrict__ out)
{
    int i = blockIdx.x * 256 + threadIdx.x;
    const float4* p = (const float4*)(g_part + (size_t)i * 4);
    float4 a = p[0], b = p[1];   // (se0,sv0,se1,sv1), (se2,sv2,se3,sv3)
    out[i] = (a.y + a.w + b.y + b.w) / (a.x + a.z + b.x + b.z);
}

// ---------------------------------------------------------------------------
// Launch
// ---------------------------------------------------------------------------
extern "C" void kernel_launch(void* const* d_in, const int* in_sizes, int n_in,
                              void* d_out, int out_size)
{
    const float* power   = (const float*)d_in[0];
    const int*   ele_idx = (const int*)  d_in[1];
    // d_in[2] = range_indices (unused by reference)
    const int*   azi_idx = (const int*)  d_in[3];
    const float* ele_tab = (const float*)d_in[4];
    const float* azi_tab = (const float*)d_in[5];
    const float* Wq      = (const float*)d_in[6];
    const float* bq      = (const float*)d_in[7];
    const float* Wk      = (const float*)d_in[8];
    const float* bk      = (const float*)d_in[9];
    const float* Wv      = (const float*)d_in[10];
    const float* bv      = (const float*)d_in[11];
    float* out = (float*)d_out;

    cudaFuncSetAttribute(qkv_mma_kernel, cudaFuncAttributeMaxDynamicSharedMemorySize, A_SMEM_BYTES);
    cudaFuncSetAttribute(attn_mma_kernel, cudaFuncAttributeMaxDynamicSharedMemorySize, B_SMEM_BYTES);

    prep_kernel<<<1, 128>>>(Wq, bq, Wk, bk, Wv, bv);
    qkv_mma_kernel<<<NROWS / 128, 256, A_SMEM_BYTES>>>(
        power, ele_idx, azi_idx, ele_tab, azi_tab);
    attn_mma_kernel<<<NUM_RANGES * 16, 256, B_SMEM_BYTES>>>();
    finalize_kernel<<<NROWS / 256, 256>>>(out);
}

// round 13
// speedup vs baseline: 2.8461x; 1.2056x over previous
#include <cuda_runtime.h>
#include <cuda_fp16.h>
#include <math.h>
#include <stdint.h>

#define NUM_RANGES 256
#define KPR 512
#define DOPPLER 64
#define EMBED 16
#define IN_DIM 96
#define NROWS (NUM_RANGES * KPR)   // 131072

// Scratch (static device allocations are permitted)
__device__ __half g_Qf[NROWS * 64];         // fp16 Q, pre-scaled by log2(e)/8
__device__ __half g_Kf[NROWS * 64];         // fp16 K
__device__ float g_vs[NROWS];
__device__ __half g_Wf[128 * 96];           // fp16 weights (rows 0..63 Wq, 64..127 Wk)
__device__ float g_wvs[96];
__device__ float g_bb[128];
__device__ float g_bvs[1];

// ---------------- mma.sync / ldmatrix helpers (sm_80+ PTX, sm_103-safe) -----
__device__ __forceinline__ unsigned smem_u32(const void* p) {
    unsigned a;
    asm("{ .reg .u64 t; cvta.to.shared.u64 t, %1; cvt.u32.u64 %0, t; }" : "=r"(a) : "l"(p));
    return a;
}
__device__ __forceinline__ void ldsm_x4(uint32_t* r, unsigned addr) {
    asm volatile("ldmatrix.sync.aligned.m8n8.x4.shared.b16 {%0,%1,%2,%3}, [%4];"
                 : "=r"(r[0]), "=r"(r[1]), "=r"(r[2]), "=r"(r[3]) : "r"(addr));
}
__device__ __forceinline__ void mma_f16(float* c, const uint32_t* a, const uint32_t* b) {
    asm volatile("mma.sync.aligned.m16n8k16.row.col.f32.f16.f16.f32 "
                 "{%0,%1,%2,%3}, {%4,%5,%6,%7}, {%8,%9}, {%0,%1,%2,%3};"
                 : "+f"(c[0]), "+f"(c[1]), "+f"(c[2]), "+f"(c[3])
                 : "r"(a[0]), "r"(a[1]), "r"(a[2]), "r"(a[3]), "r"(b[0]), "r"(b[1]));
}
__device__ __forceinline__ float ex2(float x) {
    float y; asm("ex2.approx.f32 %0, %1;" : "=f"(y) : "f"(x)); return y;
}
__device__ __forceinline__ unsigned pk(__half a, __half b) {
    return (unsigned)__half_as_ushort(a) | ((unsigned)__half_as_ushort(b) << 16);
}

#define SCQ 0.1803368801111244f   // log2(e) / sqrt(64)

// ---------------------------------------------------------------------------
// Prep kernel: one-time weight fp16 convert + wv colsums + bias staging.
// ---------------------------------------------------------------------------
__global__ void __launch_bounds__(128) prep_kernel(
    const float* __restrict__ Wq, const float* __restrict__ bq,
    const float* __restrict__ Wk, const float* __restrict__ bk,
    const float* __restrict__ Wv, const float* __restrict__ bv)
{
    const int tid = threadIdx.x;
    for (int i = tid; i < 64 * 96; i += 128) {
        int d = i / 96, f = i % 96;
        g_Wf[d * 96 + f]        = __float2half_rn(Wq[i]);
        g_Wf[(64 + d) * 96 + f] = __float2half_rn(Wk[i]);
    }
    if (tid < 96) {
        float s = 0.f;
        #pragma unroll 8
        for (int d = 0; d < 64; ++d) s += Wv[d * 96 + tid];
        g_wvs[tid] = s;
    }
    if (tid < 64) { g_bb[tid] = bq[tid]; g_bb[64 + tid] = bk[tid]; }
    if (tid == 0) {
        float s = 0.f;
        #pragma unroll 8
        for (int d = 0; d < 64; ++d) s += bv[d];
        g_bvs[0] = s;
    }
}

// ---------------------------------------------------------------------------
// Kernel A: fused gather + QK projection via mma.sync, single fp16 product.
// CTA = 128 rows x 128 outs x 96, 256 thr, 3 CTAs/SM.
// ---------------------------------------------------------------------------
#define QP 104
#define ST_P 144                            // staging row pitch (bytes)
#define AX   0
#define AW   (AX + 128 * QP * 2)            // 26624
#define A_BB (AW + 128 * QP * 2)            // 53248  float[128]
#define A_SMEM_BYTES (A_BB + 128 * 4)       // 53760

__global__ void __launch_bounds__(256, 3) qkv_mma_kernel(
    const float* __restrict__ power, const int* __restrict__ ele_idx,
    const int* __restrict__ azi_idx, const float* __restrict__ ele_tab,
    const float* __restrict__ azi_tab)
{
    extern __shared__ char smem[];
    const unsigned sbase = smem_u32(smem);
    __half* xf = (__half*)(smem + AX);
    float* sB = (float*)(smem + A_BB);

    const int tid  = threadIdx.x;
    const int row0 = blockIdx.x * 128;

    // ---- fused gather + fp16 convert + inline vsum (2 threads per row) ----
    {
        const int row = tid >> 1, half = tid & 1;
        const int grow = row0 + row;
        unsigned* xrow = (unsigned*)(xf + row * QP);
        float vacc = 0.f;

        const float4* pv = (const float4*)(power + (size_t)grow * 64 + half * 32);
        #pragma unroll
        for (int u = 0; u < 8; ++u) {
            float4 v = pv[u];
            int f = half * 32 + u * 4;
            vacc += v.x * g_wvs[f]     + v.y * g_wvs[f + 1]
                  + v.z * g_wvs[f + 2] + v.w * g_wvs[f + 3];
            xrow[f >> 1]       = pk(__float2half_rn(v.x), __float2half_rn(v.y));
            xrow[(f >> 1) + 1] = pk(__float2half_rn(v.z), __float2half_rn(v.w));
        }
        const int eidx = half ? azi_idx[grow] : ele_idx[grow];
        const float4* ev = (const float4*)((half ? azi_tab : ele_tab) + (size_t)eidx * 16);
        const int fbase = 64 + half * 16;
        #pragma unroll
        for (int u = 0; u < 4; ++u) {
            float4 v = ev[u];
            int f = fbase + u * 4;
            vacc += v.x * g_wvs[f]     + v.y * g_wvs[f + 1]
                  + v.z * g_wvs[f + 2] + v.w * g_wvs[f + 3];
            xrow[f >> 1]       = pk(__float2half_rn(v.x), __float2half_rn(v.y));
            xrow[(f >> 1) + 1] = pk(__float2half_rn(v.z), __float2half_rn(v.w));
        }
        vacc += __shfl_xor_sync(0xffffffffu, vacc, 1);
        if (!half) g_vs[grow] = vacc + g_bvs[0];
    }

    // weights: straight fp16 copies (12 uint4 chunks per 96-elem row)
    for (int i = tid; i < 128 * 12; i += 256) {
        int row = i / 12, c = i % 12;
        *(uint4*)(smem + AW + row * QP * 2 + c * 16) = *(const uint4*)&g_Wf[row * 96 + c * 8];
    }
    if (tid < 128) sB[tid] = g_bb[tid];
    __syncthreads();

    // ---- MMA: warp w = rows w*16..+15, all 128 outs, K=96 (6 chunks) ----
    const int w = tid >> 5, lane = tid & 31;
    const int qr = w * 16;
    const int arow = qr + (lane & 15);
    const int acol = (lane >> 4) * 8;
    const int brow = (lane & 7) + ((lane >> 4) << 3);
    const int bcol = ((lane >> 3) & 1) * 8;

    float C[16][4];
    #pragma unroll
    for (int nt = 0; nt < 16; ++nt)
        #pragma unroll
        for (int j = 0; j < 4; ++j) C[nt][j] = 0.f;

    #pragma unroll
    for (int dc = 0; dc < 6; ++dc) {
        uint32_t Af[4];
        unsigned aoff = (unsigned)(arow * QP + dc * 16 + acol) * 2;
        ldsm_x4(Af, sbase + AX + aoff);
        #pragma unroll
        for (int nt2 = 0; nt2 < 8; ++nt2) {
            unsigned boff = (unsigned)((nt2 * 16 + brow) * QP + dc * 16 + bcol) * 2;
            uint32_t Bf[4];
            ldsm_x4(Bf, sbase + AW + boff);
            mma_f16(C[nt2 * 2],     Af, Bf);
            mma_f16(C[nt2 * 2 + 1], Af, Bf + 2);
        }
    }
    __syncthreads();   // all ldsm reads done; smem now reusable as staging

    // ---- epilogue: bias + scale; Q,K -> fp16; stage in smem (ST_P pitch) ----
    {
        const int rl = qr + (lane >> 2);
        #pragma unroll
        for (int nt = 0; nt < 16; ++nt) {
            int cb = nt * 8 + (lane & 3) * 2;
            bool isQ = (nt < 8);
            float scl = isQ ? SCQ : 1.0f;
            int cc = isQ ? cb : (cb - 64);
            char* st = smem + (isQ ? AX : AW);
            float b0 = sB[cb], b1 = sB[cb + 1];
            float v00 = (C[nt][0] + b0) * scl, v01 = (C[nt][1] + b1) * scl;
            float v10 = (C[nt][2] + b0) * scl, v11 = (C[nt][3] + b1) * scl;
            *(unsigned*)(st + rl * ST_P + cc * 2) =
                pk(__float2half_rn(v00), __float2half_rn(v01));
            *(unsigned*)(st + (rl + 8) * ST_P + cc * 2) =
                pk(__float2half_rn(v10), __float2half_rn(v11));
        }
    }
    __syncthreads();

    // ---- copy-out: coalesced uint4 stores (2 arrays x 4 iters/thread) ----
    {
        const int offs[2] = {AX, AW};
        __half* dsts[2] = {g_Qf, g_Kf};
        #pragma unroll
        for (int a = 0; a < 2; ++a) {
            const char* src = smem + offs[a];
            __half* dst = dsts[a];
            #pragma unroll
            for (int it = 0; it < 4; ++it) {
                int i = tid + it * 256;
                int row = i >> 3, c = i & 7;
                uint4 v = *(const uint4*)(src + row * ST_P + c * 16);
                *(uint4*)&dst[(size_t)(row0 + row) * 64 + c * 8] = v;
            }
        }
    }
}

// ---------------------------------------------------------------------------
// Kernel B: mma.sync attention, full 512 k per CTA via 2-pass K streaming.
// 256 threads, 128q rows, grid = 1024 (r = bid>>2, qb = bid&3). 4 CTAs/SM.
// Direct output (no partials, no finalize).
// ---------------------------------------------------------------------------
#define QS 72
#define S_QF 0
#define S_KF (S_QF + 128 * QS * 2)          // 18432; K chunk: 256 rows x 144B
#define S_VS (S_KF + 256 * QS * 2)          // 55296; 512 floats
#define B_SMEM_BYTES (S_VS + 512 * 4)       // 57344

__global__ void __launch_bounds__(256, 4) attn_mma_kernel(float* __restrict__ out)
{
    extern __shared__ char smem[];
    const unsigned sbase = smem_u32(smem);
    const int tid = threadIdx.x;
    const int r  = blockIdx.x >> 2;
    const int qb = blockIdx.x & 3;
    const int kbase = r * KPR;
    const int qrow0 = kbase + qb * 128;

    const uint4* Qf4 = (const uint4*)g_Qf;
    const uint4* Kf4 = (const uint4*)g_Kf;

    // ---- load Qf, vsum (all 512), K chunk 0 (rows 0..255) ----
    for (int i = tid; i < 1024; i += 256) {
        int row = i >> 3, c = i & 7;
        *(uint4*)(smem + S_QF + row * QS * 2 + c * 16) = Qf4[(size_t)(qrow0 + row) * 8 + c];
    }
    for (int i = tid; i < 512; i += 256)
        *(float*)(smem + S_VS + i * 4) = g_vs[kbase + i];
    for (int i = tid; i < 2048; i += 256) {
        int row = i >> 3, c = i & 7;
        *(uint4*)(smem + S_KF + row * QS * 2 + c * 16) = Kf4[(size_t)(kbase + row) * 8 + c];
    }
    __syncthreads();

    const int w = tid >> 5, lane = tid & 31;
    const int qr = w * 16;

    // ---- resident A fragments (Qf), 4 d-chunks ----
    uint32_t Af[4][4];
    {
        int arow = qr + (lane & 15);
        int acol = (lane >> 4) * 8;
        #pragma unroll
        for (int dc = 0; dc < 4; ++dc) {
            unsigned off = (unsigned)(arow * QS + dc * 16 + acol) * 2;
            ldsm_x4(Af[dc], sbase + S_QF + off);
        }
    }

    float se0 = 0.f, sv0 = 0.f, se1 = 0.f, sv1 = 0.f;
    const int brow = (lane & 7) + ((lane >> 4) << 3);
    const int bcol = ((lane >> 3) & 1) * 8;
    const float* vsp = (const float*)(smem + S_VS);
    const int c0off = 2 * (lane & 3);

    for (int kc = 0; kc < 2; ++kc) {
        if (kc == 1) {
            __syncthreads();   // pass-0 ldsm complete before overwrite
            for (int i = tid; i < 2048; i += 256) {
                int row = i >> 3, c = i & 7;
                *(uint4*)(smem + S_KF + row * QS * 2 + c * 16) =
                    Kf4[(size_t)(kbase + 256 + row) * 8 + c];
            }
            __syncthreads();
        }

        #pragma unroll
        for (int kt = 0; kt < 8; ++kt) {      // 32 k-cols per chunk
            float C[4][4];
            #pragma unroll
            for (int nt = 0; nt < 4; ++nt)
                #pragma unroll
                for (int j = 0; j < 4; ++j) C[nt][j] = 0.f;

            #pragma unroll
            for (int dc = 0; dc < 4; ++dc) {
                #pragma unroll
                for (int nt2 = 0; nt2 < 2; ++nt2) {
                    int n0 = kt * 32 + nt2 * 16;
                    unsigned off = (unsigned)((n0 + brow) * QS + dc * 16 + bcol) * 2;
                    uint32_t Bf[4];
                    ldsm_x4(Bf, sbase + S_KF + off);
                    mma_f16(C[nt2 * 2],     Af[dc], Bf);
                    mma_f16(C[nt2 * 2 + 1], Af[dc], Bf + 2);
                }
            }

            // epilogue for this 32-k chunk (scores already in log2 units)
            #pragma unroll
            for (int nt = 0; nt < 4; ++nt) {
                int col0 = kc * 256 + kt * 32 + nt * 8 + c0off;
                float2 vv = *(const float2*)(vsp + col0);
                float e0 = ex2(C[nt][0]);
                float e1 = ex2(C[nt][1]);
                float e2 = ex2(C[nt][2]);
                float e3 = ex2(C[nt][3]);
                se0 += e0 + e1; sv0 += e0 * vv.x + e1 * vv.y;
                se1 += e2 + e3; sv1 += e2 * vv.x + e3 * vv.y;
            }
        }
    }

    // quad reduce, direct output
    #pragma unroll
    for (int o = 1; o <= 2; o <<= 1) {
        se0 += __shfl_xor_sync(0xffffffffu, se0, o);
        sv0 += __shfl_xor_sync(0xffffffffu, sv0, o);
        se1 += __shfl_xor_sync(0xffffffffu, se1, o);
        sv1 += __shfl_xor_sync(0xffffffffu, sv1, o);
    }
    if ((lane & 3) == 0) {
        int row = qrow0 + qr + (lane >> 2);
        out[row]     = sv0 / se0;
        out[row + 8] = sv1 / se1;
    }
}

// ---------------------------------------------------------------------------
// Launch
// ---------------------------------------------------------------------------
extern "C" void kernel_launch(void* const* d_in, const int* in_sizes, int n_in,
                              void* d_out, int out_size)
{
    const float* power   = (const float*)d_in[0];
    const int*   ele_idx = (const int*)  d_in[1];
    // d_in[2] = range_indices (unused by reference)
    const int*   azi_idx = (const int*)  d_in[3];
    const float* ele_tab = (const float*)d_in[4];
    const float* azi_tab = (const float*)d_in[5];
    const float* Wq      = (const float*)d_in[6];
    const float* bq      = (const float*)d_in[7];
    const float* Wk      = (const float*)d_in[8];
    const float* bk      = (const float*)d_in[9];
    const float* Wv      = (const float*)d_in[10];
    const float* bv      = (const float*)d_in[11];
    float* out = (float*)d_out;

    cudaFuncSetAttribute(qkv_mma_kernel, cudaFuncAttributeMaxDynamicSharedMemorySize, A_SMEM_BYTES);
    cudaFuncSetAttribute(attn_mma_kernel, cudaFuncAttributeMaxDynamicSharedMemorySize, B_SMEM_BYTES);

    prep_kernel<<<1, 128>>>(Wq, bq, Wk, bk, Wv, bv);
    qkv_mma_kernel<<<NROWS / 128, 256, A_SMEM_BYTES>>>(
        power, ele_idx, azi_idx, ele_tab, azi_tab);
    attn_mma_kernel<<<NUM_RANGES * 4, 256, B_SMEM_BYTES>>>(out);
}

// round 14
// speedup vs baseline: 3.0129x; 1.0586x over previous
#include <cuda_runtime.h>
#include <cuda_fp16.h>
#include <math.h>
#include <stdint.h>

#define NUM_RANGES 256
#define KPR 512
#define DOPPLER 64
#define EMBED 16
#define IN_DIM 96
#define NROWS (NUM_RANGES * KPR)   // 131072

// Scratch (static device allocations are permitted)
__device__ __half g_Qf[NROWS * 64];         // fp16 Q, pre-scaled by log2(e)/8
__device__ __half g_Kf[NROWS * 64];         // fp16 K
__device__ float g_vs[NROWS];
__device__ __half g_Wf[128 * 96];           // fp16 weights (rows 0..63 Wq, 64..127 Wk)
__device__ float g_wvs[96];
__device__ float g_bb[128];
__device__ float g_bvs[1];

// ---------------- mma.sync / ldmatrix helpers (sm_80+ PTX, sm_103-safe) -----
__device__ __forceinline__ unsigned smem_u32(const void* p) {
    unsigned a;
    asm("{ .reg .u64 t; cvta.to.shared.u64 t, %1; cvt.u32.u64 %0, t; }" : "=r"(a) : "l"(p));
    return a;
}
__device__ __forceinline__ void ldsm_x4(uint32_t* r, unsigned addr) {
    asm volatile("ldmatrix.sync.aligned.m8n8.x4.shared.b16 {%0,%1,%2,%3}, [%4];"
                 : "=r"(r[0]), "=r"(r[1]), "=r"(r[2]), "=r"(r[3]) : "r"(addr));
}
__device__ __forceinline__ void mma_f16(float* c, const uint32_t* a, const uint32_t* b) {
    asm volatile("mma.sync.aligned.m16n8k16.row.col.f32.f16.f16.f32 "
                 "{%0,%1,%2,%3}, {%4,%5,%6,%7}, {%8,%9}, {%0,%1,%2,%3};"
                 : "+f"(c[0]), "+f"(c[1]), "+f"(c[2]), "+f"(c[3])
                 : "r"(a[0]), "r"(a[1]), "r"(a[2]), "r"(a[3]), "r"(b[0]), "r"(b[1]));
}
__device__ __forceinline__ float ex2(float x) {
    float y; asm("ex2.approx.f32 %0, %1;" : "=f"(y) : "f"(x)); return y;
}
__device__ __forceinline__ unsigned pk(__half a, __half b) {
    return (unsigned)__half_as_ushort(a) | ((unsigned)__half_as_ushort(b) << 16);
}

#define SCQ 0.1803368801111244f   // log2(e) / sqrt(64)

// ---------------------------------------------------------------------------
// Prep kernel (parallel): 16 CTAs x 256 threads.
// - fp16 weight convert spread over all 4096 threads
// - wvs: one warp per column (96 warps), lane sums 2 elems, shfl tree
// - bvs: warp 96; bias copies: threads < 64
// ---------------------------------------------------------------------------
__global__ void __launch_bounds__(256) prep_kernel(
    const float* __restrict__ Wq, const float* __restrict__ bq,
    const float* __restrict__ Wk, const float* __restrict__ bk,
    const float* __restrict__ Wv, const float* __restrict__ bv)
{
    const int gt = blockIdx.x * 256 + threadIdx.x;   // 0..4095
    const int lane = gt & 31, gw = gt >> 5;          // warp 0..127

    // weight conversion: 6144 (d,f) pairs over 4096 threads
    for (int i = gt; i < 64 * 96; i += 4096) {
        int d = i / 96, f = i % 96;
        g_Wf[d * 96 + f]        = __float2half_rn(Wq[i]);
        g_Wf[(64 + d) * 96 + f] = __float2half_rn(Wk[i]);
    }

    if (gw < 96) {
        // column sum of Wv over d (warp per column f = gw)
        float s = Wv[(size_t)(lane * 2) * 96 + gw] + Wv[(size_t)(lane * 2 + 1) * 96 + gw];
        #pragma unroll
        for (int o = 16; o > 0; o >>= 1) s += __shfl_xor_sync(0xffffffffu, s, o);
        if (lane == 0) g_wvs[gw] = s;
    } else if (gw == 96) {
        float s = bv[lane * 2] + bv[lane * 2 + 1];
        #pragma unroll
        for (int o = 16; o > 0; o >>= 1) s += __shfl_xor_sync(0xffffffffu, s, o);
        if (lane == 0) g_bvs[0] = s;
    } else if (gw >= 98 && gw < 100) {
        int t = (gw - 98) * 32 + lane;   // 0..63
        g_bb[t] = bq[t]; g_bb[64 + t] = bk[t];
    }
}

// ---------------------------------------------------------------------------
// Kernel A: fused gather + QK projection via mma.sync, single fp16 product.
// CTA = 128 rows x 128 outs x 96, 256 thr, 3 CTAs/SM.
// ---------------------------------------------------------------------------
#define QP 104
#define ST_P 144                            // staging row pitch (bytes)
#define AX   0
#define AW   (AX + 128 * QP * 2)            // 26624
#define A_BB (AW + 128 * QP * 2)            // 53248  float[128]
#define A_SMEM_BYTES (A_BB + 128 * 4)       // 53760

__global__ void __launch_bounds__(256, 3) qkv_mma_kernel(
    const float* __restrict__ power, const int* __restrict__ ele_idx,
    const int* __restrict__ azi_idx, const float* __restrict__ ele_tab,
    const float* __restrict__ azi_tab)
{
    extern __shared__ char smem[];
    const unsigned sbase = smem_u32(smem);
    __half* xf = (__half*)(smem + AX);
    float* sB = (float*)(smem + A_BB);

    const int tid  = threadIdx.x;
    const int row0 = blockIdx.x * 128;

    // ---- fused gather + fp16 convert + inline vsum (2 threads per row) ----
    {
        const int row = tid >> 1, half = tid & 1;
        const int grow = row0 + row;
        unsigned* xrow = (unsigned*)(xf + row * QP);
        float vacc = 0.f;

        const float4* pv = (const float4*)(power + (size_t)grow * 64 + half * 32);
        #pragma unroll
        for (int u = 0; u < 8; ++u) {
            float4 v = pv[u];
            int f = half * 32 + u * 4;
            vacc += v.x * g_wvs[f]     + v.y * g_wvs[f + 1]
                  + v.z * g_wvs[f + 2] + v.w * g_wvs[f + 3];
            xrow[f >> 1]       = pk(__float2half_rn(v.x), __float2half_rn(v.y));
            xrow[(f >> 1) + 1] = pk(__float2half_rn(v.z), __float2half_rn(v.w));
        }
        const int eidx = half ? azi_idx[grow] : ele_idx[grow];
        const float4* ev = (const float4*)((half ? azi_tab : ele_tab) + (size_t)eidx * 16);
        const int fbase = 64 + half * 16;
        #pragma unroll
        for (int u = 0; u < 4; ++u) {
            float4 v = ev[u];
            int f = fbase + u * 4;
            vacc += v.x * g_wvs[f]     + v.y * g_wvs[f + 1]
                  + v.z * g_wvs[f + 2] + v.w * g_wvs[f + 3];
            xrow[f >> 1]       = pk(__float2half_rn(v.x), __float2half_rn(v.y));
            xrow[(f >> 1) + 1] = pk(__float2half_rn(v.z), __float2half_rn(v.w));
        }
        vacc += __shfl_xor_sync(0xffffffffu, vacc, 1);
        if (!half) g_vs[grow] = vacc + g_bvs[0];
    }

    // weights: straight fp16 copies (12 uint4 chunks per 96-elem row)
    for (int i = tid; i < 128 * 12; i += 256) {
        int row = i / 12, c = i % 12;
        *(uint4*)(smem + AW + row * QP * 2 + c * 16) = *(const uint4*)&g_Wf[row * 96 + c * 8];
    }
    if (tid < 128) sB[tid] = g_bb[tid];
    __syncthreads();

    // ---- MMA: warp w = rows w*16..+15, all 128 outs, K=96 (6 chunks) ----
    const int w = tid >> 5, lane = tid & 31;
    const int qr = w * 16;
    const int arow = qr + (lane & 15);
    const int acol = (lane >> 4) * 8;
    const int brow = (lane & 7) + ((lane >> 4) << 3);
    const int bcol = ((lane >> 3) & 1) * 8;

    float C[16][4];
    #pragma unroll
    for (int nt = 0; nt < 16; ++nt)
        #pragma unroll
        for (int j = 0; j < 4; ++j) C[nt][j] = 0.f;

    #pragma unroll
    for (int dc = 0; dc < 6; ++dc) {
        uint32_t Af[4];
        unsigned aoff = (unsigned)(arow * QP + dc * 16 + acol) * 2;
        ldsm_x4(Af, sbase + AX + aoff);
        #pragma unroll
        for (int nt2 = 0; nt2 < 8; ++nt2) {
            unsigned boff = (unsigned)((nt2 * 16 + brow) * QP + dc * 16 + bcol) * 2;
            uint32_t Bf[4];
            ldsm_x4(Bf, sbase + AW + boff);
            mma_f16(C[nt2 * 2],     Af, Bf);
            mma_f16(C[nt2 * 2 + 1], Af, Bf + 2);
        }
    }
    __syncthreads();   // all ldsm reads done; smem now reusable as staging

    // ---- epilogue: bias + scale; Q,K -> fp16; stage in smem (ST_P pitch) ----
    {
        const int rl = qr + (lane >> 2);
        #pragma unroll
        for (int nt = 0; nt < 16; ++nt) {
            int cb = nt * 8 + (lane & 3) * 2;
            bool isQ = (nt < 8);
            float scl = isQ ? SCQ : 1.0f;
            int cc = isQ ? cb : (cb - 64);
            char* st = smem + (isQ ? AX : AW);
            float b0 = sB[cb], b1 = sB[cb + 1];
            float v00 = (C[nt][0] + b0) * scl, v01 = (C[nt][1] + b1) * scl;
            float v10 = (C[nt][2] + b0) * scl, v11 = (C[nt][3] + b1) * scl;
            *(unsigned*)(st + rl * ST_P + cc * 2) =
                pk(__float2half_rn(v00), __float2half_rn(v01));
            *(unsigned*)(st + (rl + 8) * ST_P + cc * 2) =
                pk(__float2half_rn(v10), __float2half_rn(v11));
        }
    }
    __syncthreads();

    // ---- copy-out: coalesced uint4 stores (2 arrays x 4 iters/thread) ----
    {
        const int offs[2] = {AX, AW};
        __half* dsts[2] = {g_Qf, g_Kf};
        #pragma unroll
        for (int a = 0; a < 2; ++a) {
            const char* src = smem + offs[a];
            __half* dst = dsts[a];
            #pragma unroll
            for (int it = 0; it < 4; ++it) {
                int i = tid + it * 256;
                int row = i >> 3, c = i & 7;
                uint4 v = *(const uint4*)(src + row * ST_P + c * 16);
                *(uint4*)&dst[(size_t)(row0 + row) * 64 + c * 8] = v;
            }
        }
    }
}

// ---------------------------------------------------------------------------
// Kernel B: mma.sync attention, full 512 k per CTA via 2-pass K streaming.
// 256 threads, 128q rows, grid = 1024 (r = bid>>2, qb = bid&3). 4 CTAs/SM.
// Direct output (no partials, no finalize).
// ---------------------------------------------------------------------------
#define QS 72
#define S_QF 0
#define S_KF (S_QF + 128 * QS * 2)          // 18432; K chunk: 256 rows x 144B
#define S_VS (S_KF + 256 * QS * 2)          // 55296; 512 floats
#define B_SMEM_BYTES (S_VS + 512 * 4)       // 57344

__global__ void __launch_bounds__(256, 4) attn_mma_kernel(float* __restrict__ out)
{
    extern __shared__ char smem[];
    const unsigned sbase = smem_u32(smem);
    const int tid = threadIdx.x;
    const int r  = blockIdx.x >> 2;
    const int qb = blockIdx.x & 3;
    const int kbase = r * KPR;
    const int qrow0 = kbase + qb * 128;

    const uint4* Qf4 = (const uint4*)g_Qf;
    const uint4* Kf4 = (const uint4*)g_Kf;

    // ---- load Qf, vsum (all 512), K chunk 0 (rows 0..255) ----
    for (int i = tid; i < 1024; i += 256) {
        int row = i >> 3, c = i & 7;
        *(uint4*)(smem + S_QF + row * QS * 2 + c * 16) = Qf4[(size_t)(qrow0 + row) * 8 + c];
    }
    for (int i = tid; i < 512; i += 256)
        *(float*)(smem + S_VS + i * 4) = g_vs[kbase + i];
    for (int i = tid; i < 2048; i += 256) {
        int row = i >> 3, c = i & 7;
        *(uint4*)(smem + S_KF + row * QS * 2 + c * 16) = Kf4[(size_t)(kbase + row) * 8 + c];
    }
    __syncthreads();

    const int w = tid >> 5, lane = tid & 31;
    const int qr = w * 16;

    // ---- resident A fragments (Qf), 4 d-chunks ----
    uint32_t Af[4][4];
    {
        int arow = qr + (lane & 15);
        int acol = (lane >> 4) * 8;
        #pragma unroll
        for (int dc = 0; dc < 4; ++dc) {
            unsigned off = (unsigned)(arow * QS + dc * 16 + acol) * 2;
            ldsm_x4(Af[dc], sbase + S_QF + off);
        }
    }

    float se0 = 0.f, sv0 = 0.f, se1 = 0.f, sv1 = 0.f;
    const int brow = (lane & 7) + ((lane >> 4) << 3);
    const int bcol = ((lane >> 3) & 1) * 8;
    const float* vsp = (const float*)(smem + S_VS);
    const int c0off = 2 * (lane & 3);

    for (int kc = 0; kc < 2; ++kc) {
        if (kc == 1) {
            __syncthreads();   // pass-0 ldsm complete before overwrite
            for (int i = tid; i < 2048; i += 256) {
                int row = i >> 3, c = i & 7;
                *(uint4*)(smem + S_KF + row * QS * 2 + c * 16) =
                    Kf4[(size_t)(kbase + 256 + row) * 8 + c];
            }
            __syncthreads();
        }

        #pragma unroll
        for (int kt = 0; kt < 8; ++kt) {      // 32 k-cols per chunk
            float C[4][4];
            #pragma unroll
            for (int nt = 0; nt < 4; ++nt)
                #pragma unroll
                for (int j = 0; j < 4; ++j) C[nt][j] = 0.f;

            #pragma unroll
            for (int dc = 0; dc < 4; ++dc) {
                #pragma unroll
                for (int nt2 = 0; nt2 < 2; ++nt2) {
                    int n0 = kt * 32 + nt2 * 16;
                    unsigned off = (unsigned)((n0 + brow) * QS + dc * 16 + bcol) * 2;
                    uint32_t Bf[4];
                    ldsm_x4(Bf, sbase + S_KF + off);
                    mma_f16(C[nt2 * 2],     Af[dc], Bf);
                    mma_f16(C[nt2 * 2 + 1], Af[dc], Bf + 2);
                }
            }

            // epilogue for this 32-k chunk (scores already in log2 units)
            #pragma unroll
            for (int nt = 0; nt < 4; ++nt) {
                int col0 = kc * 256 + kt * 32 + nt * 8 + c0off;
                float2 vv = *(const float2*)(vsp + col0);
                float e0 = ex2(C[nt][0]);
                float e1 = ex2(C[nt][1]);
                float e2 = ex2(C[nt][2]);
                float e3 = ex2(C[nt][3]);
                se0 += e0 + e1; sv0 += e0 * vv.x + e1 * vv.y;
                se1 += e2 + e3; sv1 += e2 * vv.x + e3 * vv.y;
            }
        }
    }

    // quad reduce, direct output
    #pragma unroll
    for (int o = 1; o <= 2; o <<= 1) {
        se0 += __shfl_xor_sync(0xffffffffu, se0, o);
        sv0 += __shfl_xor_sync(0xffffffffu, sv0, o);
        se1 += __shfl_xor_sync(0xffffffffu, se1, o);
        sv1 += __shfl_xor_sync(0xffffffffu, sv1, o);
    }
    if ((lane & 3) == 0) {
        int row = qrow0 + qr + (lane >> 2);
        out[row]     = sv0 / se0;
        out[row + 8] = sv1 / se1;
    }
}

// ---------------------------------------------------------------------------
// Launch
// ---------------------------------------------------------------------------
extern "C" void kernel_launch(void* const* d_in, const int* in_sizes, int n_in,
                              void* d_out, int out_size)
{
    const float* power   = (const float*)d_in[0];
    const int*   ele_idx = (const int*)  d_in[1];
    // d_in[2] = range_indices (unused by reference)
    const int*   azi_idx = (const int*)  d_in[3];
    const float* ele_tab = (const float*)d_in[4];
    const float* azi_tab = (const float*)d_in[5];
    const float* Wq      = (const float*)d_in[6];
    const float* bq      = (const float*)d_in[7];
    const float* Wk      = (const float*)d_in[8];
    const float* bk      = (const float*)d_in[9];
    const float* Wv      = (const float*)d_in[10];
    const float* bv      = (const float*)d_in[11];
    float* out = (float*)d_out;

    cudaFuncSetAttribute(qkv_mma_kernel, cudaFuncAttributeMaxDynamicSharedMemorySize, A_SMEM_BYTES);
    cudaFuncSetAttribute(attn_mma_kernel, cudaFuncAttributeMaxDynamicSharedMemorySize, B_SMEM_BYTES);

    prep_kernel<<<16, 256>>>(Wq, bq, Wk, bk, Wv, bv);
    qkv_mma_kernel<<<NROWS / 128, 256, A_SMEM_BYTES>>>(
        power, ele_idx, azi_idx, ele_tab, azi_tab);
    attn_mma_kernel<<<NUM_RANGES * 4, 256, B_SMEM_BYTES>>>(out);
}